// round 1
// baseline (speedup 1.0000x reference)
#include <cuda_runtime.h>
#include <cuda_bf16.h>

#define BATCH  16
#define NTOK   1029
#define NHEAD  16
#define HDIM   64
#define DMODEL 1024
#define NPOS   1024
#define PREFIX 5          // NTOK - NPOS
#define BNROWS (BATCH * NTOK)   // 16464

// Scratch (static device allocations — allowed; no cudaMalloc anywhere)
__device__ float g_q[BATCH * NHEAD * NTOK * HDIM];   // [b][h][n][d]
__device__ float g_k[BATCH * NHEAD * NTOK * HDIM];
__device__ float g_v[BATCH * NHEAD * NTOK * HDIM];
__device__ float g_ctx[BNROWS * DMODEL];             // [b*n][h*64+d]

// ---------------------------------------------------------------------------
// Fused QKV projection:  y = X @ W^T + b, scattered into [B,H,N,HD] buffers.
// Tile 64x64, K-tile 16. 256 threads, each computes 4x4.
// ---------------------------------------------------------------------------
__global__ __launch_bounds__(256) void qkv_gemm_kernel(
    const float* __restrict__ X,
    const float* __restrict__ Wq, const float* __restrict__ bq,
    const float* __restrict__ Wk, const float* __restrict__ bk,
    const float* __restrict__ Wv, const float* __restrict__ bv)
{
    __shared__ float As[16][68];   // [kk][row]
    __shared__ float Bs[16][68];   // [kk][col]

    const int tid = threadIdx.x;
    const int tx = tid & 15, ty = tid >> 4;
    const int row0 = blockIdx.x * 64;
    const int col0 = blockIdx.y * 64;           // 0..3071
    const int wsel = col0 >> 10;                // 0=q 1=k 2=v
    const float* W    = (wsel == 0) ? Wq : ((wsel == 1) ? Wk : Wv);
    const float* bias = (wsel == 0) ? bq : ((wsel == 1) ? bk : bv);
    float* dst        = (wsel == 0) ? g_q : ((wsel == 1) ? g_k : g_v);
    const int c0loc = col0 & 1023;

    float acc[4][4] = {};

    for (int kt = 0; kt < DMODEL; kt += 16) {
        #pragma unroll
        for (int t = 0; t < 4; t++) {
            int idx = tid + t * 256;
            int r = idx >> 4, kk = idx & 15;
            int gr = row0 + r;
            As[kk][r] = (gr < BNROWS) ? X[gr * DMODEL + kt + kk] : 0.f;
            Bs[kk][r] = W[(c0loc + r) * DMODEL + kt + kk];
        }
        __syncthreads();
        #pragma unroll
        for (int kk = 0; kk < 16; kk++) {
            float4 av  = *(const float4*)&As[kk][ty * 4];
            float4 bv4 = *(const float4*)&Bs[kk][tx * 4];
            float a[4] = {av.x, av.y, av.z, av.w};
            float b[4] = {bv4.x, bv4.y, bv4.z, bv4.w};
            #pragma unroll
            for (int i = 0; i < 4; i++)
                #pragma unroll
                for (int j = 0; j < 4; j++)
                    acc[i][j] += a[i] * b[j];
        }
        __syncthreads();
    }

    #pragma unroll
    for (int i = 0; i < 4; i++) {
        int r = row0 + ty * 4 + i;
        if (r >= BNROWS) continue;
        int b_ = r / NTOK;
        int n  = r - b_ * NTOK;
        #pragma unroll
        for (int j = 0; j < 4; j++) {
            int cl = c0loc + tx * 4 + j;
            int h = cl >> 6, d = cl & 63;
            dst[(((b_ * NHEAD + h) * NTOK + n) << 6) + d] = acc[i][j] + bias[cl];
        }
    }
}

// ---------------------------------------------------------------------------
// RoPE on q and k (in-place, last NPOS positions). One thread per (d, d+32) pair.
// idx layout: [sel(1)][b(4)][h(4)][pos(10)][d(5)] = 2 * 2^23 threads
// ---------------------------------------------------------------------------
__global__ __launch_bounds__(256) void rope_kernel(
    const float* __restrict__ sinp, const float* __restrict__ cosp)
{
    int idx = blockIdx.x * 256 + threadIdx.x;
    float* base = (idx & (1 << 23)) ? g_k : g_q;
    int r   = idx & ((1 << 23) - 1);
    int d   = r & 31;
    int pos = (r >> 5) & 1023;
    int h   = (r >> 15) & 15;
    int b   = r >> 19;
    float* p = base + (((b * NHEAD + h) * NTOK + (PREFIX + pos)) << 6);
    float x1 = p[d], x2 = p[d + 32];
    float c1 = cosp[pos * 64 + d],      s1 = sinp[pos * 64 + d];
    float c2 = cosp[pos * 64 + d + 32], s2 = sinp[pos * 64 + d + 32];
    p[d]      = x1 * c1 - x2 * s1;      // rotate_half: first half gets -x2
    p[d + 32] = x2 * c2 + x1 * s2;      // second half gets +x1
}

// ---------------------------------------------------------------------------
// Flash-style attention. Block = (q-tile of 64, head, batch). 256 threads.
// smem: qs [d][tok], ks [d][tok], vs [tok][d], ps [kj][qi], all pitch 68.
// Each thread owns a 4x4 micro-tile of scores and of the output.
// ---------------------------------------------------------------------------
__global__ __launch_bounds__(256) void attn_kernel()
{
    extern __shared__ float sm[];
    float* qs = sm;                 // 64*68
    float* ks = sm + 64 * 68;
    float* vs = sm + 2 * 64 * 68;
    float* ps = sm + 3 * 64 * 68;

    const int tid = threadIdx.x;
    const int tx = tid & 15, ty = tid >> 4;
    const int b = blockIdx.z, h = blockIdx.y;
    const int q0 = blockIdx.x * 64;

    const float* qp = g_q + (((b * NHEAD + h) * NTOK) << 6);
    const float* kp = g_k + (((b * NHEAD + h) * NTOK) << 6);
    const float* vp = g_v + (((b * NHEAD + h) * NTOK) << 6);

    // load q tile transposed: qs[d][tok]
    for (int t = 0; t < 16; t++) {
        int idx = tid + t * 256;
        int tok = idx >> 6, d = idx & 63;
        int g = q0 + tok;
        qs[d * 68 + tok] = (g < NTOK) ? qp[(g << 6) + d] : 0.f;
    }

    float acc[4][4] = {};
    float m_run[4], l_run[4];
    #pragma unroll
    for (int i = 0; i < 4; i++) { m_run[i] = -1e30f; l_run[i] = 0.f; }

    for (int k0 = 0; k0 < NTOK; k0 += 64) {
        __syncthreads();   // prev-iter ps/vs consumed; also publishes qs on iter 0
        // load k transposed
        for (int t = 0; t < 16; t++) {
            int idx = tid + t * 256;
            int tok = idx >> 6, d = idx & 63;
            int g = k0 + tok;
            ks[d * 68 + tok] = (g < NTOK) ? kp[(g << 6) + d] : 0.f;
        }
        // load v natural [tok][d] via float4
        #pragma unroll
        for (int t = 0; t < 4; t++) {
            int idx = tid + t * 256;
            int tok = idx >> 4, d4 = idx & 15;
            int g = k0 + tok;
            float4 val = (g < NTOK) ? *(const float4*)&vp[(g << 6) + d4 * 4]
                                    : make_float4(0.f, 0.f, 0.f, 0.f);
            *(float4*)&vs[tok * 68 + d4 * 4] = val;
        }
        __syncthreads();

        // S = scale * Q K^T   (4x4 per thread)
        float st[4][4] = {};
        #pragma unroll 16
        for (int d = 0; d < 64; d++) {
            float4 qv = *(const float4*)&qs[d * 68 + ty * 4];
            float4 kv = *(const float4*)&ks[d * 68 + tx * 4];
            float a[4] = {qv.x, qv.y, qv.z, qv.w};
            float c[4] = {kv.x, kv.y, kv.z, kv.w};
            #pragma unroll
            for (int i = 0; i < 4; i++)
                #pragma unroll
                for (int j = 0; j < 4; j++)
                    st[i][j] += a[i] * c[j];
        }
        #pragma unroll
        for (int i = 0; i < 4; i++)
            #pragma unroll
            for (int j = 0; j < 4; j++) {
                st[i][j] *= 0.125f;                 // HD^-0.5
                if (k0 + tx * 4 + j >= NTOK) st[i][j] = -1e30f;
            }

        // online softmax per q-row (16 lanes with same ty share a row group)
        #pragma unroll
        for (int i = 0; i < 4; i++) {
            float mx = fmaxf(fmaxf(st[i][0], st[i][1]), fmaxf(st[i][2], st[i][3]));
            #pragma unroll
            for (int off = 8; off; off >>= 1)
                mx = fmaxf(mx, __shfl_xor_sync(0xffffffffu, mx, off));
            float mt = fmaxf(m_run[i], mx);
            float alpha = __expf(m_run[i] - mt);
            m_run[i] = mt;
            float rs = 0.f;
            #pragma unroll
            for (int j = 0; j < 4; j++) {
                st[i][j] = __expf(st[i][j] - mt);
                rs += st[i][j];
            }
            #pragma unroll
            for (int off = 8; off; off >>= 1)
                rs += __shfl_xor_sync(0xffffffffu, rs, off);
            l_run[i] = l_run[i] * alpha + rs;
            #pragma unroll
            for (int j = 0; j < 4; j++) acc[i][j] *= alpha;
        }

        // publish P transposed: ps[kj][qi]
        #pragma unroll
        for (int i = 0; i < 4; i++)
            #pragma unroll
            for (int j = 0; j < 4; j++)
                ps[(tx * 4 + j) * 68 + ty * 4 + i] = st[i][j];
        __syncthreads();

        // O += P V
        #pragma unroll 16
        for (int kk = 0; kk < 64; kk++) {
            float4 pv = *(const float4*)&ps[kk * 68 + ty * 4];
            float4 vv = *(const float4*)&vs[kk * 68 + tx * 4];
            float a[4] = {pv.x, pv.y, pv.z, pv.w};
            float c[4] = {vv.x, vv.y, vv.z, vv.w};
            #pragma unroll
            for (int i = 0; i < 4; i++)
                #pragma unroll
                for (int j = 0; j < 4; j++)
                    acc[i][j] += a[i] * c[j];
        }
    }

    // epilogue -> g_ctx [b*n][h*64+d]
    #pragma unroll
    for (int i = 0; i < 4; i++) {
        int qg = q0 + ty * 4 + i;
        if (qg >= NTOK) continue;
        float inv = 1.f / l_run[i];
        #pragma unroll
        for (int j = 0; j < 4; j++)
            g_ctx[(b * NTOK + qg) * DMODEL + (h << 6) + tx * 4 + j] = acc[i][j] * inv;
    }
}

// ---------------------------------------------------------------------------
// Output projection: out = ctx @ Wo^T + bo
// ---------------------------------------------------------------------------
__global__ __launch_bounds__(256) void out_gemm_kernel(
    const float* __restrict__ Wo, const float* __restrict__ bo,
    float* __restrict__ out)
{
    __shared__ float As[16][68];
    __shared__ float Bs[16][68];

    const int tid = threadIdx.x;
    const int tx = tid & 15, ty = tid >> 4;
    const int row0 = blockIdx.x * 64;
    const int col0 = blockIdx.y * 64;

    float acc[4][4] = {};

    for (int kt = 0; kt < DMODEL; kt += 16) {
        #pragma unroll
        for (int t = 0; t < 4; t++) {
            int idx = tid + t * 256;
            int r = idx >> 4, kk = idx & 15;
            int gr = row0 + r;
            As[kk][r] = (gr < BNROWS) ? g_ctx[gr * DMODEL + kt + kk] : 0.f;
            Bs[kk][r] = Wo[(col0 + r) * DMODEL + kt + kk];
        }
        __syncthreads();
        #pragma unroll
        for (int kk = 0; kk < 16; kk++) {
            float4 av  = *(const float4*)&As[kk][ty * 4];
            float4 bv4 = *(const float4*)&Bs[kk][tx * 4];
            float a[4] = {av.x, av.y, av.z, av.w};
            float b[4] = {bv4.x, bv4.y, bv4.z, bv4.w};
            #pragma unroll
            for (int i = 0; i < 4; i++)
                #pragma unroll
                for (int j = 0; j < 4; j++)
                    acc[i][j] += a[i] * b[j];
        }
        __syncthreads();
    }

    #pragma unroll
    for (int i = 0; i < 4; i++) {
        int r = row0 + ty * 4 + i;
        if (r >= BNROWS) continue;
        #pragma unroll
        for (int j = 0; j < 4; j++) {
            int c = col0 + tx * 4 + j;
            out[r * DMODEL + c] = acc[i][j] + bo[c];
        }
    }
}

// ---------------------------------------------------------------------------
extern "C" void kernel_launch(void* const* d_in, const int* in_sizes, int n_in,
                              void* d_out, int out_size)
{
    const float* hs   = (const float*)d_in[0];
    const float* sinp = (const float*)d_in[1];
    const float* cosp = (const float*)d_in[2];
    const float* Wq   = (const float*)d_in[3];
    const float* bq   = (const float*)d_in[4];
    const float* Wk   = (const float*)d_in[5];
    const float* bk   = (const float*)d_in[6];
    const float* Wv   = (const float*)d_in[7];
    const float* bv   = (const float*)d_in[8];
    const float* Wo   = (const float*)d_in[9];
    const float* bo   = (const float*)d_in[10];
    float* out = (float*)d_out;

    // 68 KB dynamic smem for attention (attribute set is capture-safe, idempotent)
    cudaFuncSetAttribute(attn_kernel,
                         cudaFuncAttributeMaxDynamicSharedMemorySize, 4 * 64 * 68 * 4);

    qkv_gemm_kernel<<<dim3(258, 48), 256>>>(hs, Wq, bq, Wk, bk, Wv, bv);
    rope_kernel<<<(2 * (1 << 23)) / 256, 256>>>(sinp, cosp);
    attn_kernel<<<dim3(17, NHEAD, BATCH), 256, 4 * 64 * 68 * 4>>>();
    out_gemm_kernel<<<dim3(258, 16), 256>>>(Wo, bo, out);
}

// round 3
// speedup vs baseline: 1.7626x; 1.7626x over previous
#include <cuda_runtime.h>
#include <cuda_bf16.h>
#include <cstdint>

#define BATCH  16
#define NTOK   1029
#define NHEAD  16
#define HDIM   64
#define DMODEL 1024
#define NPOS   1024
#define PREFIX 5
#define BNROWS (BATCH * NTOK)   // 16464

// ---------------- scratch ----------------
__device__ float g_q[BATCH * NHEAD * NTOK * HDIM];
__device__ float g_k[BATCH * NHEAD * NTOK * HDIM];
__device__ float g_v[BATCH * NHEAD * NTOK * HDIM];
__device__ float g_ctx[BNROWS * DMODEL];

__device__ __nv_bfloat16 g_xhi[BNROWS * DMODEL];
__device__ __nv_bfloat16 g_xlo[BNROWS * DMODEL];
__device__ __nv_bfloat16 g_whi[3 * DMODEL * DMODEL];
__device__ __nv_bfloat16 g_wlo[3 * DMODEL * DMODEL];
__device__ __nv_bfloat16 g_wohi[DMODEL * DMODEL];
__device__ __nv_bfloat16 g_wolo[DMODEL * DMODEL];
__device__ __nv_bfloat16 g_chi[BNROWS * DMODEL];
__device__ __nv_bfloat16 g_clo[BNROWS * DMODEL];
__device__ float g_bqkv[3 * DMODEL];

// ---------------- helpers ----------------
__device__ __forceinline__ uint32_t s2u(const void* p) {
    return (uint32_t)__cvta_generic_to_shared(p);
}
__device__ __forceinline__ void cp16(uint32_t d, const void* s, bool v) {
    asm volatile("cp.async.cg.shared.global [%0], [%1], 16, %2;"
                 :: "r"(d), "l"(s), "r"(v ? 16u : 0u));
}
#define LDSM4(r, addr) \
    asm volatile("ldmatrix.sync.aligned.m8n8.x4.shared.b16 {%0,%1,%2,%3}, [%4];" \
        : "=r"((r)[0]), "=r"((r)[1]), "=r"((r)[2]), "=r"((r)[3]) : "r"(addr))
#define MMA16816(c, a, b0, b1) \
    asm volatile("mma.sync.aligned.m16n8k16.row.col.f32.bf16.bf16.f32 " \
        "{%0,%1,%2,%3}, {%4,%5,%6,%7}, {%8,%9}, {%0,%1,%2,%3};" \
        : "+f"((c)[0]), "+f"((c)[1]), "+f"((c)[2]), "+f"((c)[3]) \
        : "r"((a)[0]), "r"((a)[1]), "r"((a)[2]), "r"((a)[3]), "r"(b0), "r"(b1))

// ---------------- conversion kernels ----------------
__global__ __launch_bounds__(256) void split_x_kernel(const float* __restrict__ in) {
    int i = blockIdx.x * 256 + threadIdx.x;
    float x = in[i];
    __nv_bfloat16 h = __float2bfloat16(x);
    g_xhi[i] = h;
    g_xlo[i] = __float2bfloat16(x - __bfloat162float(h));
}
__global__ __launch_bounds__(256) void split_w_kernel(
    const float* __restrict__ Wq, const float* __restrict__ Wk,
    const float* __restrict__ Wv, const float* __restrict__ Wo) {
    int i = blockIdx.x * 256 + threadIdx.x;
    const int M1 = DMODEL * DMODEL;
    if (i < 3 * M1) {
        float x = (i < M1) ? Wq[i] : ((i < 2 * M1) ? Wk[i - M1] : Wv[i - 2 * M1]);
        __nv_bfloat16 h = __float2bfloat16(x);
        g_whi[i] = h;
        g_wlo[i] = __float2bfloat16(x - __bfloat162float(h));
    } else {
        int j = i - 3 * M1;
        float x = Wo[j];
        __nv_bfloat16 h = __float2bfloat16(x);
        g_wohi[j] = h;
        g_wolo[j] = __float2bfloat16(x - __bfloat162float(h));
    }
}
__global__ __launch_bounds__(256) void biaspack_kernel(
    const float* __restrict__ bq, const float* __restrict__ bk,
    const float* __restrict__ bv) {
    int i = blockIdx.x * 256 + threadIdx.x;
    if (i < 3 * DMODEL) {
        const float* s = (i < DMODEL) ? bq : ((i < 2 * DMODEL) ? bk : bv);
        g_bqkv[i] = s[i & (DMODEL - 1)];
    }
}
__global__ __launch_bounds__(256) void split_ctx_kernel() {
    int i = blockIdx.x * 256 + threadIdx.x;
    float x = g_ctx[i];
    __nv_bfloat16 h = __float2bfloat16(x);
    g_chi[i] = h;
    g_clo[i] = __float2bfloat16(x - __bfloat162float(h));
}

// ---------------- warp-MMA split-bf16 GEMM ----------------
// C[M,N] = A[M,K] @ B[N,K]^T (+bias).  CTA tile 128x128, K-stage 32.
// 8 warps (2x4): each warp 64x32 via m16n8k16, 3-way split accumulation.
#define BK 32
#define NKIT (DMODEL / BK)          // 32
#define SROWB 80                    // smem row pitch bytes (40 bf16)
#define BUFB  (128 * SROWB)         // 10240 B per matrix
#define STAGEB (4 * BUFB)           // Ahi|Alo|Bhi|Blo = 40960 B
#define GSM_BYTES (2 * STAGEB)      // 81920 B

__global__ __launch_bounds__(256) void wm_gemm_kernel(
    const float* __restrict__ bias_out, float* __restrict__ outp, int qkv_mode)
{
    extern __shared__ char sm[];
    const uint32_t sb = s2u(sm);
    const int tid = threadIdx.x;
    const int wid = tid >> 5, lane = tid & 31;
    const int warp_m = wid & 1, warp_n = wid >> 1;
    const int row0 = blockIdx.y * 128;
    const int col0 = blockIdx.x * 128;

    const __nv_bfloat16* Ahi = qkv_mode ? g_xhi : g_chi;
    const __nv_bfloat16* Alo = qkv_mode ? g_xlo : g_clo;
    const __nv_bfloat16* Bhi = qkv_mode ? g_whi : g_wohi;
    const __nv_bfloat16* Blo = qkv_mode ? g_wlo : g_wolo;

    float acc[4][4][4] = {};

    // per-thread load slots: 512 16B-chunks per matrix, 2 per thread
    int c0 = tid, c1 = tid + 256;
    int r0_ = c0 >> 2, k0_ = c0 & 3;
    int r1_ = c1 >> 2, k1_ = c1 & 3;

    auto load_stage = [&](int kt, int buf) {
        const size_t kb = (size_t)kt * (BK * 2);
        const uint32_t s0 = sb + buf * STAGEB;
        // chunk 0
        {
            uint32_t so = r0_ * SROWB + k0_ * 16;
            int ga = row0 + r0_;
            bool av = ga < BNROWS;
            size_t goA = (size_t)(av ? ga : 0) * (DMODEL * 2) + kb + k0_ * 16;
            size_t goB = (size_t)(col0 + r0_) * (DMODEL * 2) + kb + k0_ * 16;
            cp16(s0 + so,             (const char*)Ahi + goA, av);
            cp16(s0 + BUFB + so,      (const char*)Alo + goA, av);
            cp16(s0 + 2 * BUFB + so,  (const char*)Bhi + goB, true);
            cp16(s0 + 3 * BUFB + so,  (const char*)Blo + goB, true);
        }
        // chunk 1
        {
            uint32_t so = r1_ * SROWB + k1_ * 16;
            int ga = row0 + r1_;
            bool av = ga < BNROWS;
            size_t goA = (size_t)(av ? ga : 0) * (DMODEL * 2) + kb + k1_ * 16;
            size_t goB = (size_t)(col0 + r1_) * (DMODEL * 2) + kb + k1_ * 16;
            cp16(s0 + so,             (const char*)Ahi + goA, av);
            cp16(s0 + BUFB + so,      (const char*)Alo + goA, av);
            cp16(s0 + 2 * BUFB + so,  (const char*)Bhi + goB, true);
            cp16(s0 + 3 * BUFB + so,  (const char*)Blo + goB, true);
        }
        asm volatile("cp.async.commit_group;");
    };

    load_stage(0, 0);

    // ldmatrix lane addressing
    const int a_row = warp_m * 64 + (lane & 15);
    const int a_colsel = (lane >> 4) << 3;           // 0 or 8
    const int b_row = warp_n * 32 + ((lane >> 4) & 1) * 8 + (lane & 7);
    const int b_colsel = ((lane >> 3) & 1) << 3;     // 0 or 8

    for (int kt = 0; kt < NKIT; kt++) {
        if (kt + 1 < NKIT) load_stage(kt + 1, (kt + 1) & 1);
        if (kt + 1 < NKIT) asm volatile("cp.async.wait_group 1;" ::: "memory");
        else               asm volatile("cp.async.wait_group 0;" ::: "memory");
        __syncthreads();

        const uint32_t sA_hi = sb + (kt & 1) * STAGEB;
        const uint32_t sA_lo = sA_hi + BUFB;
        const uint32_t sB_hi = sA_hi + 2 * BUFB;
        const uint32_t sB_lo = sA_hi + 3 * BUFB;

        #pragma unroll
        for (int kk = 0; kk < BK; kk += 16) {
            uint32_t ah[4][4], al[4][4], bh[2][4], bl[2][4];
            #pragma unroll
            for (int mt = 0; mt < 4; mt++) {
                uint32_t off = (uint32_t)(a_row + mt * 16) * SROWB
                             + (uint32_t)(kk + a_colsel) * 2;
                LDSM4(ah[mt], sA_hi + off);
                LDSM4(al[mt], sA_lo + off);
            }
            #pragma unroll
            for (int p = 0; p < 2; p++) {
                uint32_t off = (uint32_t)(b_row + p * 16) * SROWB
                             + (uint32_t)(kk + b_colsel) * 2;
                LDSM4(bh[p], sB_hi + off);
                LDSM4(bl[p], sB_lo + off);
            }
            #pragma unroll
            for (int mt = 0; mt < 4; mt++)
                #pragma unroll
                for (int nt = 0; nt < 4; nt++) {
                    int p = nt >> 1, q = (nt & 1) * 2;
                    MMA16816(acc[mt][nt], ah[mt], bh[p][q], bh[p][q + 1]);
                    MMA16816(acc[mt][nt], ah[mt], bl[p][q], bl[p][q + 1]);
                    MMA16816(acc[mt][nt], al[mt], bh[p][q], bh[p][q + 1]);
                }
        }
        __syncthreads();
    }

    // epilogue
    const int crow = row0 + warp_m * 64 + (lane >> 2);
    const int ccol = col0 + warp_n * 32 + (lane & 3) * 2;
    #pragma unroll
    for (int mt = 0; mt < 4; mt++) {
        #pragma unroll
        for (int rr = 0; rr < 2; rr++) {
            int R = crow + mt * 16 + rr * 8;
            if (R >= BNROWS) continue;
            int b_ = R / NTOK, n = R - b_ * NTOK;
            #pragma unroll
            for (int nt = 0; nt < 4; nt++) {
                float v0 = acc[mt][nt][rr * 2 + 0];
                float v1 = acc[mt][nt][rr * 2 + 1];
                int C = ccol + nt * 8;
                if (qkv_mode) {
                    #pragma unroll
                    for (int e = 0; e < 2; e++) {
                        int Ce = C + e;
                        float val = (e ? v1 : v0) + g_bqkv[Ce];
                        int wsel = Ce >> 10, cl = Ce & 1023, h = cl >> 6, d = cl & 63;
                        float* dst = (wsel == 0) ? g_q : ((wsel == 1) ? g_k : g_v);
                        dst[(size_t)((b_ * NHEAD + h) * NTOK + n) * 64 + d] = val;
                    }
                } else {
                    outp[(size_t)R * DMODEL + C]     = v0 + bias_out[C];
                    outp[(size_t)R * DMODEL + C + 1] = v1 + bias_out[C + 1];
                }
            }
        }
    }
}

// ---------------- RoPE ----------------
__global__ __launch_bounds__(256) void rope_kernel(
    const float* __restrict__ sinp, const float* __restrict__ cosp)
{
    int idx = blockIdx.x * 256 + threadIdx.x;
    float* base = (idx & (1 << 23)) ? g_k : g_q;
    int r   = idx & ((1 << 23) - 1);
    int d   = r & 31;
    int pos = (r >> 5) & 1023;
    int h   = (r >> 15) & 15;
    int b   = r >> 19;
    float* p = base + (((b * NHEAD + h) * NTOK + (PREFIX + pos)) << 6);
    float x1 = p[d], x2 = p[d + 32];
    float c1 = cosp[pos * 64 + d],      s1 = sinp[pos * 64 + d];
    float c2 = cosp[pos * 64 + d + 32], s2 = sinp[pos * 64 + d + 32];
    p[d]      = x1 * c1 - x2 * s1;
    p[d + 32] = x2 * c2 + x1 * s2;
}

// ---------------- flash attention (fp32) ----------------
__global__ __launch_bounds__(256) void attn_kernel()
{
    extern __shared__ float smf[];
    float* qs = smf;
    float* ks = smf + 64 * 68;
    float* vs = smf + 2 * 64 * 68;
    float* ps = smf + 3 * 64 * 68;

    const int tid = threadIdx.x;
    const int tx = tid & 15, ty = tid >> 4;
    const int b = blockIdx.z, h = blockIdx.y;
    const int q0 = blockIdx.x * 64;

    const float* qp = g_q + (((size_t)(b * NHEAD + h) * NTOK) << 6);
    const float* kp = g_k + (((size_t)(b * NHEAD + h) * NTOK) << 6);
    const float* vp = g_v + (((size_t)(b * NHEAD + h) * NTOK) << 6);

    for (int t = 0; t < 16; t++) {
        int idx = tid + t * 256;
        int tok = idx >> 6, d = idx & 63;
        int g = q0 + tok;
        qs[d * 68 + tok] = (g < NTOK) ? qp[(g << 6) + d] : 0.f;
    }

    float acc[4][4] = {};
    float m_run[4], l_run[4];
    #pragma unroll
    for (int i = 0; i < 4; i++) { m_run[i] = -1e30f; l_run[i] = 0.f; }

    for (int k0 = 0; k0 < NTOK; k0 += 64) {
        __syncthreads();
        for (int t = 0; t < 16; t++) {
            int idx = tid + t * 256;
            int tok = idx >> 6, d = idx & 63;
            int g = k0 + tok;
            ks[d * 68 + tok] = (g < NTOK) ? kp[(g << 6) + d] : 0.f;
        }
        #pragma unroll
        for (int t = 0; t < 4; t++) {
            int idx = tid + t * 256;
            int tok = idx >> 4, d4 = idx & 15;
            int g = k0 + tok;
            float4 val = (g < NTOK) ? *(const float4*)&vp[(g << 6) + d4 * 4]
                                    : make_float4(0.f, 0.f, 0.f, 0.f);
            *(float4*)&vs[tok * 68 + d4 * 4] = val;
        }
        __syncthreads();

        float st[4][4] = {};
        #pragma unroll 16
        for (int d = 0; d < 64; d++) {
            float4 qv = *(const float4*)&qs[d * 68 + ty * 4];
            float4 kv = *(const float4*)&ks[d * 68 + tx * 4];
            float a[4] = {qv.x, qv.y, qv.z, qv.w};
            float c[4] = {kv.x, kv.y, kv.z, kv.w};
            #pragma unroll
            for (int i = 0; i < 4; i++)
                #pragma unroll
                for (int j = 0; j < 4; j++)
                    st[i][j] += a[i] * c[j];
        }
        #pragma unroll
        for (int i = 0; i < 4; i++)
            #pragma unroll
            for (int j = 0; j < 4; j++) {
                st[i][j] *= 0.125f;
                if (k0 + tx * 4 + j >= NTOK) st[i][j] = -1e30f;
            }

        #pragma unroll
        for (int i = 0; i < 4; i++) {
            float mx = fmaxf(fmaxf(st[i][0], st[i][1]), fmaxf(st[i][2], st[i][3]));
            #pragma unroll
            for (int off = 8; off; off >>= 1)
                mx = fmaxf(mx, __shfl_xor_sync(0xffffffffu, mx, off));
            float mt = fmaxf(m_run[i], mx);
            float alpha = __expf(m_run[i] - mt);
            m_run[i] = mt;
            float rs = 0.f;
            #pragma unroll
            for (int j = 0; j < 4; j++) {
                st[i][j] = __expf(st[i][j] - mt);
                rs += st[i][j];
            }
            #pragma unroll
            for (int off = 8; off; off >>= 1)
                rs += __shfl_xor_sync(0xffffffffu, rs, off);
            l_run[i] = l_run[i] * alpha + rs;
            #pragma unroll
            for (int j = 0; j < 4; j++) acc[i][j] *= alpha;
        }

        #pragma unroll
        for (int i = 0; i < 4; i++)
            #pragma unroll
            for (int j = 0; j < 4; j++)
                ps[(tx * 4 + j) * 68 + ty * 4 + i] = st[i][j];
        __syncthreads();

        #pragma unroll 16
        for (int kk = 0; kk < 64; kk++) {
            float4 pv = *(const float4*)&ps[kk * 68 + ty * 4];
            float4 vv = *(const float4*)&vs[kk * 68 + tx * 4];
            float a[4] = {pv.x, pv.y, pv.z, pv.w};
            float c[4] = {vv.x, vv.y, vv.z, vv.w};
            #pragma unroll
            for (int i = 0; i < 4; i++)
                #pragma unroll
                for (int j = 0; j < 4; j++)
                    acc[i][j] += a[i] * c[j];
        }
    }

    #pragma unroll
    for (int i = 0; i < 4; i++) {
        int qg = q0 + ty * 4 + i;
        if (qg >= NTOK) continue;
        float inv = 1.f / l_run[i];
        #pragma unroll
        for (int j = 0; j < 4; j++)
            g_ctx[(size_t)(b * NTOK + qg) * DMODEL + (h << 6) + tx * 4 + j] =
                acc[i][j] * inv;
    }
}

// ---------------------------------------------------------------------------
extern "C" void kernel_launch(void* const* d_in, const int* in_sizes, int n_in,
                              void* d_out, int out_size)
{
    const float* hs   = (const float*)d_in[0];
    const float* sinp = (const float*)d_in[1];
    const float* cosp = (const float*)d_in[2];
    const float* Wq   = (const float*)d_in[3];
    const float* bq   = (const float*)d_in[4];
    const float* Wk   = (const float*)d_in[5];
    const float* bk   = (const float*)d_in[6];
    const float* Wv   = (const float*)d_in[7];
    const float* bv   = (const float*)d_in[8];
    const float* Wo   = (const float*)d_in[9];
    const float* bo   = (const float*)d_in[10];
    float* out = (float*)d_out;

    cudaFuncSetAttribute(wm_gemm_kernel,
                         cudaFuncAttributeMaxDynamicSharedMemorySize, GSM_BYTES);
    cudaFuncSetAttribute(attn_kernel,
                         cudaFuncAttributeMaxDynamicSharedMemorySize, 4 * 64 * 68 * 4);

    split_x_kernel<<<(BNROWS * DMODEL) / 256, 256>>>(hs);
    split_w_kernel<<<(4 * DMODEL * DMODEL) / 256, 256>>>(Wq, Wk, Wv, Wo);
    biaspack_kernel<<<12, 256>>>(bq, bk, bv);

    wm_gemm_kernel<<<dim3(3 * DMODEL / 128, (BNROWS + 127) / 128), 256, GSM_BYTES>>>(
        bo, out, 1);

    rope_kernel<<<(2 * (1 << 23)) / 256, 256>>>(sinp, cosp);
    attn_kernel<<<dim3(17, NHEAD, BATCH), 256, 4 * 64 * 68 * 4>>>();

    split_ctx_kernel<<<(BNROWS * DMODEL) / 256, 256>>>();
    wm_gemm_kernel<<<dim3(DMODEL / 128, (BNROWS + 127) / 128), 256, GSM_BYTES>>>(
        bo, out, 0);
}

// round 4
// speedup vs baseline: 3.0723x; 1.7431x over previous
#include <cuda_runtime.h>
#include <cuda_bf16.h>
#include <cstdint>

#define BATCH  16
#define NTOK   1029
#define NHEAD  16
#define HDIM   64
#define DMODEL 1024
#define PREFIX 5
#define BNROWS (BATCH * NTOK)   // 16464
#define BHN    (BATCH * NHEAD * NTOK)

// ---------------- scratch ----------------
__device__ float g_q[BHN * HDIM];
__device__ float g_k[BHN * HDIM];
__device__ float g_v[BHN * HDIM];

__device__ __nv_bfloat16 g_xhi[BNROWS * DMODEL];
__device__ __nv_bfloat16 g_xlo[BNROWS * DMODEL];
__device__ __nv_bfloat16 g_whi[3 * DMODEL * DMODEL];
__device__ __nv_bfloat16 g_wlo[3 * DMODEL * DMODEL];
__device__ __nv_bfloat16 g_wohi[DMODEL * DMODEL];
__device__ __nv_bfloat16 g_wolo[DMODEL * DMODEL];
__device__ __nv_bfloat16 g_chi[BNROWS * DMODEL];
__device__ __nv_bfloat16 g_clo[BNROWS * DMODEL];
__device__ float g_bqkv[3 * DMODEL];

__device__ __nv_bfloat16 g_qhi[BHN * HDIM];
__device__ __nv_bfloat16 g_qlo[BHN * HDIM];
__device__ __nv_bfloat16 g_khi[BHN * HDIM];
__device__ __nv_bfloat16 g_klo[BHN * HDIM];
__device__ __nv_bfloat16 g_vhi[BHN * HDIM];
__device__ __nv_bfloat16 g_vlo[BHN * HDIM];

// ---------------- helpers ----------------
__device__ __forceinline__ uint32_t s2u(const void* p) {
    return (uint32_t)__cvta_generic_to_shared(p);
}
__device__ __forceinline__ void cp16(uint32_t d, const void* s, bool v) {
    asm volatile("cp.async.cg.shared.global [%0], [%1], 16, %2;"
                 :: "r"(d), "l"(s), "r"(v ? 16u : 0u));
}
#define LDSM4(r, addr) \
    asm volatile("ldmatrix.sync.aligned.m8n8.x4.shared.b16 {%0,%1,%2,%3}, [%4];" \
        : "=r"((r)[0]), "=r"((r)[1]), "=r"((r)[2]), "=r"((r)[3]) : "r"(addr))
#define LDSM4T(r, addr) \
    asm volatile("ldmatrix.sync.aligned.m8n8.x4.trans.shared.b16 {%0,%1,%2,%3}, [%4];" \
        : "=r"((r)[0]), "=r"((r)[1]), "=r"((r)[2]), "=r"((r)[3]) : "r"(addr))
#define MMA16816(c, a, b0, b1) \
    asm volatile("mma.sync.aligned.m16n8k16.row.col.f32.bf16.bf16.f32 " \
        "{%0,%1,%2,%3}, {%4,%5,%6,%7}, {%8,%9}, {%0,%1,%2,%3};" \
        : "+f"((c)[0]), "+f"((c)[1]), "+f"((c)[2]), "+f"((c)[3]) \
        : "r"((a)[0]), "r"((a)[1]), "r"((a)[2]), "r"((a)[3]), "r"(b0), "r"(b1))

__device__ __forceinline__ void split2(float a, float b, uint32_t& hi, uint32_t& lo) {
    __nv_bfloat162 h = __floats2bfloat162_rn(a, b);
    float ra = a - __bfloat162float(h.x);
    float rb = b - __bfloat162float(h.y);
    __nv_bfloat162 l = __floats2bfloat162_rn(ra, rb);
    hi = *(uint32_t*)&h;
    lo = *(uint32_t*)&l;
}

// ---------------- conversion kernels ----------------
__global__ __launch_bounds__(256) void split_x_kernel(const float* __restrict__ in) {
    int i = blockIdx.x * 256 + threadIdx.x;
    float x = in[i];
    __nv_bfloat16 h = __float2bfloat16(x);
    g_xhi[i] = h;
    g_xlo[i] = __float2bfloat16(x - __bfloat162float(h));
}
__global__ __launch_bounds__(256) void split_w_kernel(
    const float* __restrict__ Wq, const float* __restrict__ Wk,
    const float* __restrict__ Wv, const float* __restrict__ Wo) {
    int i = blockIdx.x * 256 + threadIdx.x;
    const int M1 = DMODEL * DMODEL;
    if (i < 3 * M1) {
        float x = (i < M1) ? Wq[i] : ((i < 2 * M1) ? Wk[i - M1] : Wv[i - 2 * M1]);
        __nv_bfloat16 h = __float2bfloat16(x);
        g_whi[i] = h;
        g_wlo[i] = __float2bfloat16(x - __bfloat162float(h));
    } else {
        int j = i - 3 * M1;
        float x = Wo[j];
        __nv_bfloat16 h = __float2bfloat16(x);
        g_wohi[j] = h;
        g_wolo[j] = __float2bfloat16(x - __bfloat162float(h));
    }
}
__global__ __launch_bounds__(256) void biaspack_kernel(
    const float* __restrict__ bq, const float* __restrict__ bk,
    const float* __restrict__ bv) {
    int i = blockIdx.x * 256 + threadIdx.x;
    if (i < 3 * DMODEL) {
        const float* s = (i < DMODEL) ? bq : ((i < 2 * DMODEL) ? bk : bv);
        g_bqkv[i] = s[i & (DMODEL - 1)];
    }
}

// ---------------- prep: RoPE + bf16 split of q,k,v ----------------
// idx = t * (BHN*32) + (bh*NTOK + n)*32 + d,  t in {0=q,1=k,2=v}, d in 0..31
__global__ __launch_bounds__(256) void prep_kernel(
    const float* __restrict__ sinp, const float* __restrict__ cosp)
{
    int idx = blockIdx.x * 256 + threadIdx.x;
    const int per = BATCH * NHEAD * NTOK * 32;
    int t = idx / per;
    int r = idx - t * per;
    int d = r & 31;
    int rowi = r >> 5;                 // bh*NTOK + n
    int n = rowi % NTOK;

    const float* src = (t == 0) ? g_q : ((t == 1) ? g_k : g_v);
    __nv_bfloat16* dhi = (t == 0) ? g_qhi : ((t == 1) ? g_khi : g_vhi);
    __nv_bfloat16* dlo = (t == 0) ? g_qlo : ((t == 1) ? g_klo : g_vlo);

    size_t base = (size_t)rowi * 64;
    float x1 = src[base + d], x2 = src[base + d + 32];
    float y1 = x1, y2 = x2;
    if (t < 2 && n >= PREFIX) {
        int pos = n - PREFIX;
        float c1 = cosp[pos * 64 + d],      s1 = sinp[pos * 64 + d];
        float c2 = cosp[pos * 64 + d + 32], s2 = sinp[pos * 64 + d + 32];
        y1 = x1 * c1 - x2 * s1;
        y2 = x2 * c2 + x1 * s2;
    }
    __nv_bfloat16 h1 = __float2bfloat16(y1);
    __nv_bfloat16 h2 = __float2bfloat16(y2);
    dhi[base + d]      = h1;
    dhi[base + d + 32] = h2;
    dlo[base + d]      = __float2bfloat16(y1 - __bfloat162float(h1));
    dlo[base + d + 32] = __float2bfloat16(y2 - __bfloat162float(h2));
}

// ---------------- warp-MMA split-bf16 GEMM (unchanged from R3) ----------------
#define BK 32
#define NKIT (DMODEL / BK)
#define SROWB 80
#define BUFB  (128 * SROWB)
#define STAGEB (4 * BUFB)
#define GSM_BYTES (2 * STAGEB)

__global__ __launch_bounds__(256) void wm_gemm_kernel(
    const float* __restrict__ bias_out, float* __restrict__ outp, int qkv_mode)
{
    extern __shared__ char sm[];
    const uint32_t sb = s2u(sm);
    const int tid = threadIdx.x;
    const int wid = tid >> 5, lane = tid & 31;
    const int warp_m = wid & 1, warp_n = wid >> 1;
    const int row0 = blockIdx.y * 128;
    const int col0 = blockIdx.x * 128;

    const __nv_bfloat16* Ahi = qkv_mode ? g_xhi : g_chi;
    const __nv_bfloat16* Alo = qkv_mode ? g_xlo : g_clo;
    const __nv_bfloat16* Bhi = qkv_mode ? g_whi : g_wohi;
    const __nv_bfloat16* Blo = qkv_mode ? g_wlo : g_wolo;

    float acc[4][4][4] = {};

    int c0 = tid, c1 = tid + 256;
    int r0_ = c0 >> 2, k0_ = c0 & 3;
    int r1_ = c1 >> 2, k1_ = c1 & 3;

    auto load_stage = [&](int kt, int buf) {
        const size_t kb = (size_t)kt * (BK * 2);
        const uint32_t s0 = sb + buf * STAGEB;
        {
            uint32_t so = r0_ * SROWB + k0_ * 16;
            int ga = row0 + r0_;
            bool av = ga < BNROWS;
            size_t goA = (size_t)(av ? ga : 0) * (DMODEL * 2) + kb + k0_ * 16;
            size_t goB = (size_t)(col0 + r0_) * (DMODEL * 2) + kb + k0_ * 16;
            cp16(s0 + so,             (const char*)Ahi + goA, av);
            cp16(s0 + BUFB + so,      (const char*)Alo + goA, av);
            cp16(s0 + 2 * BUFB + so,  (const char*)Bhi + goB, true);
            cp16(s0 + 3 * BUFB + so,  (const char*)Blo + goB, true);
        }
        {
            uint32_t so = r1_ * SROWB + k1_ * 16;
            int ga = row0 + r1_;
            bool av = ga < BNROWS;
            size_t goA = (size_t)(av ? ga : 0) * (DMODEL * 2) + kb + k1_ * 16;
            size_t goB = (size_t)(col0 + r1_) * (DMODEL * 2) + kb + k1_ * 16;
            cp16(s0 + so,             (const char*)Ahi + goA, av);
            cp16(s0 + BUFB + so,      (const char*)Alo + goA, av);
            cp16(s0 + 2 * BUFB + so,  (const char*)Bhi + goB, true);
            cp16(s0 + 3 * BUFB + so,  (const char*)Blo + goB, true);
        }
        asm volatile("cp.async.commit_group;");
    };

    load_stage(0, 0);

    const int a_row = warp_m * 64 + (lane & 15);
    const int a_colsel = (lane >> 4) << 3;
    const int b_row = warp_n * 32 + ((lane >> 4) & 1) * 8 + (lane & 7);
    const int b_colsel = ((lane >> 3) & 1) << 3;

    for (int kt = 0; kt < NKIT; kt++) {
        if (kt + 1 < NKIT) load_stage(kt + 1, (kt + 1) & 1);
        if (kt + 1 < NKIT) asm volatile("cp.async.wait_group 1;" ::: "memory");
        else               asm volatile("cp.async.wait_group 0;" ::: "memory");
        __syncthreads();

        const uint32_t sA_hi = sb + (kt & 1) * STAGEB;
        const uint32_t sA_lo = sA_hi + BUFB;
        const uint32_t sB_hi = sA_hi + 2 * BUFB;
        const uint32_t sB_lo = sA_hi + 3 * BUFB;

        #pragma unroll
        for (int kk = 0; kk < BK; kk += 16) {
            uint32_t ah[4][4], al[4][4], bh[2][4], bl[2][4];
            #pragma unroll
            for (int mt = 0; mt < 4; mt++) {
                uint32_t off = (uint32_t)(a_row + mt * 16) * SROWB
                             + (uint32_t)(kk + a_colsel) * 2;
                LDSM4(ah[mt], sA_hi + off);
                LDSM4(al[mt], sA_lo + off);
            }
            #pragma unroll
            for (int p = 0; p < 2; p++) {
                uint32_t off = (uint32_t)(b_row + p * 16) * SROWB
                             + (uint32_t)(kk + b_colsel) * 2;
                LDSM4(bh[p], sB_hi + off);
                LDSM4(bl[p], sB_lo + off);
            }
            #pragma unroll
            for (int mt = 0; mt < 4; mt++)
                #pragma unroll
                for (int nt = 0; nt < 4; nt++) {
                    int p = nt >> 1, q = (nt & 1) * 2;
                    MMA16816(acc[mt][nt], ah[mt], bh[p][q], bh[p][q + 1]);
                    MMA16816(acc[mt][nt], ah[mt], bl[p][q], bl[p][q + 1]);
                    MMA16816(acc[mt][nt], al[mt], bh[p][q], bh[p][q + 1]);
                }
        }
        __syncthreads();
    }

    const int crow = row0 + warp_m * 64 + (lane >> 2);
    const int ccol = col0 + warp_n * 32 + (lane & 3) * 2;
    #pragma unroll
    for (int mt = 0; mt < 4; mt++) {
        #pragma unroll
        for (int rr = 0; rr < 2; rr++) {
            int R = crow + mt * 16 + rr * 8;
            if (R >= BNROWS) continue;
            int b_ = R / NTOK, n = R - b_ * NTOK;
            #pragma unroll
            for (int nt = 0; nt < 4; nt++) {
                float v0 = acc[mt][nt][rr * 2 + 0];
                float v1 = acc[mt][nt][rr * 2 + 1];
                int C = ccol + nt * 8;
                if (qkv_mode) {
                    #pragma unroll
                    for (int e = 0; e < 2; e++) {
                        int Ce = C + e;
                        float val = (e ? v1 : v0) + g_bqkv[Ce];
                        int wsel = Ce >> 10, cl = Ce & 1023, h = cl >> 6, d = cl & 63;
                        float* dst = (wsel == 0) ? g_q : ((wsel == 1) ? g_k : g_v);
                        dst[(size_t)((b_ * NHEAD + h) * NTOK + n) * 64 + d] = val;
                    }
                } else {
                    outp[(size_t)R * DMODEL + C]     = v0 + bias_out[C];
                    outp[(size_t)R * DMODEL + C + 1] = v1 + bias_out[C + 1];
                }
            }
        }
    }
}

// ---------------- tensor-core flash attention ----------------
// Block: 128 q-rows, one (b,h). 8 warps, warp w owns q rows 16w..16w+15,
// all 64 S columns (8 n-tiles) -> softmax is quad-shuffle only.
// K/V tiles of 64 kv, double-buffered cp.async. All operands split bf16.
#define APB 144                       // smem row pitch bytes (72 bf16)
#define SM_QHI 0
#define SM_QLO (128 * APB)            // 18432
#define SM_ST0 (2 * 128 * APB)        // 36864
#define STG_SZ (4 * 64 * APB)         // 36864 (khi|klo|vhi|vlo)
#define OFF_KHI 0
#define OFF_KLO (64 * APB)
#define OFF_VHI (2 * 64 * APB)
#define OFF_VLO (3 * 64 * APB)
#define ATT_SMEM (SM_ST0 + 2 * STG_SZ)  // 110592
#define NKV 17                        // ceil(1029/64)

__global__ __launch_bounds__(256, 2) void attn_tc_kernel()
{
    extern __shared__ char sm[];
    const uint32_t sb = s2u(sm);
    const int tid = threadIdx.x;
    const int wid = tid >> 5, lane = tid & 31;
    const int b = blockIdx.z, h = blockIdx.y;
    const int q0 = blockIdx.x * 128;
    const size_t base = (size_t)(b * NHEAD + h) * NTOK;   // row base

    // ---- issue Q load (group 0, together with KV tile 0) ----
    {
        #pragma unroll
        for (int t = 0; t < 8; t++) {
            int chunk = tid + t * 256;          // 2048 chunks (hi:1024, lo:1024)
            int mq = chunk >> 10, rem = chunk & 1023;
            int r = rem >> 3, c = rem & 7;
            int gr = q0 + r;
            bool v = gr < NTOK;
            size_t go = (base + (v ? gr : 0)) * 128 + c * 16;   // bytes (64 bf16/row)
            const char* src = mq ? (const char*)g_qlo : (const char*)g_qhi;
            cp16(sb + (mq ? SM_QLO : SM_QHI) + r * APB + c * 16, src + go, v);
        }
    }
    auto load_kv = [&](int i, int buf) {
        int k0 = i * 64;
        #pragma unroll
        for (int t = 0; t < 8; t++) {
            int chunk = tid + t * 256;          // 2048 chunks: 4 mats x 512
            int mat = chunk >> 9, rem = chunk & 511;
            int r = rem >> 3, c = rem & 7;
            int gr = k0 + r;
            bool v = gr < NTOK;
            size_t go = (base + (v ? gr : 0)) * 128 + c * 16;
            const char* src = (mat == 0) ? (const char*)g_khi
                            : (mat == 1) ? (const char*)g_klo
                            : (mat == 2) ? (const char*)g_vhi
                                         : (const char*)g_vlo;
            cp16(sb + SM_ST0 + buf * STG_SZ + mat * (64 * APB) + r * APB + c * 16,
                 src + go, v);
        }
    };
    load_kv(0, 0);
    asm volatile("cp.async.commit_group;");
    load_kv(1, 1);
    asm volatile("cp.async.commit_group;");
    asm volatile("cp.async.wait_group 1;" ::: "memory");
    __syncthreads();

    float oacc[8][4] = {};
    float m_run[2] = {-1e30f, -1e30f};
    float l_run[2] = {0.f, 0.f};

    // ldmatrix addressing
    const int la_row = lane & 15, la_cs = (lane >> 4) * 16;      // A frags
    const int m_ = lane >> 3, r_ = lane & 7;                     // x4 matrix id/row

    for (int i = 0; i < NKV; i++) {
        const uint32_t st = sb + SM_ST0 + (i & 1) * STG_SZ;
        const int k0 = i * 64;

        // ---- S = scale * Q K^T (split: qh*kh + qh*kl + ql*kh) ----
        float sacc[8][4] = {};
        #pragma unroll
        for (int ks = 0; ks < 4; ks++) {
            uint32_t qh[4], ql[4];
            uint32_t qoff = (uint32_t)(wid * 16 + la_row) * APB + (uint32_t)(ks * 32 + la_cs);
            LDSM4(qh, sb + SM_QHI + qoff);
            LDSM4(ql, sb + SM_QLO + qoff);
            #pragma unroll
            for (int ntp = 0; ntp < 4; ntp++) {
                uint32_t kh[4], kl[4];
                uint32_t koff = (uint32_t)(ntp * 16 + ((m_ >> 1) & 1) * 8 + r_) * APB
                              + (uint32_t)(ks * 32 + (m_ & 1) * 16);
                LDSM4(kh, st + OFF_KHI + koff);
                LDSM4(kl, st + OFF_KLO + koff);
                MMA16816(sacc[2 * ntp],     qh, kh[0], kh[1]);
                MMA16816(sacc[2 * ntp],     qh, kl[0], kl[1]);
                MMA16816(sacc[2 * ntp],     ql, kh[0], kh[1]);
                MMA16816(sacc[2 * ntp + 1], qh, kh[2], kh[3]);
                MMA16816(sacc[2 * ntp + 1], qh, kl[2], kl[3]);
                MMA16816(sacc[2 * ntp + 1], ql, kh[2], kh[3]);
            }
        }

        // ---- scale + mask + online softmax (rows g and g+8) ----
        float tm0 = -1e30f, tm1 = -1e30f;
        #pragma unroll
        for (int nt = 0; nt < 8; nt++) {
            int cbase = k0 + nt * 8 + (lane & 3) * 2;
            #pragma unroll
            for (int e = 0; e < 4; e++) {
                float sv = sacc[nt][e] * 0.125f;
                if (cbase + (e & 1) >= NTOK) sv = -1e30f;
                sacc[nt][e] = sv;
            }
            tm0 = fmaxf(tm0, fmaxf(sacc[nt][0], sacc[nt][1]));
            tm1 = fmaxf(tm1, fmaxf(sacc[nt][2], sacc[nt][3]));
        }
        tm0 = fmaxf(tm0, __shfl_xor_sync(0xffffffffu, tm0, 1));
        tm0 = fmaxf(tm0, __shfl_xor_sync(0xffffffffu, tm0, 2));
        tm1 = fmaxf(tm1, __shfl_xor_sync(0xffffffffu, tm1, 1));
        tm1 = fmaxf(tm1, __shfl_xor_sync(0xffffffffu, tm1, 2));
        float mn0 = fmaxf(m_run[0], tm0), mn1 = fmaxf(m_run[1], tm1);
        float al0 = __expf(m_run[0] - mn0), al1 = __expf(m_run[1] - mn1);
        m_run[0] = mn0; m_run[1] = mn1;

        float rs0 = 0.f, rs1 = 0.f;
        #pragma unroll
        for (int nt = 0; nt < 8; nt++) {
            sacc[nt][0] = __expf(sacc[nt][0] - mn0);
            sacc[nt][1] = __expf(sacc[nt][1] - mn0);
            sacc[nt][2] = __expf(sacc[nt][2] - mn1);
            sacc[nt][3] = __expf(sacc[nt][3] - mn1);
            rs0 += sacc[nt][0] + sacc[nt][1];
            rs1 += sacc[nt][2] + sacc[nt][3];
        }
        rs0 += __shfl_xor_sync(0xffffffffu, rs0, 1);
        rs0 += __shfl_xor_sync(0xffffffffu, rs0, 2);
        rs1 += __shfl_xor_sync(0xffffffffu, rs1, 1);
        rs1 += __shfl_xor_sync(0xffffffffu, rs1, 2);
        l_run[0] = l_run[0] * al0 + rs0;
        l_run[1] = l_run[1] * al1 + rs1;
        #pragma unroll
        for (int nt = 0; nt < 8; nt++) {
            oacc[nt][0] *= al0; oacc[nt][1] *= al0;
            oacc[nt][2] *= al1; oacc[nt][3] *= al1;
        }

        // ---- O += P V (split: ph*vh + ph*vl + pl*vh) ----
        #pragma unroll
        for (int kc = 0; kc < 4; kc++) {
            uint32_t ph[4], pl[4];
            split2(sacc[2 * kc][0],     sacc[2 * kc][1],     ph[0], pl[0]);
            split2(sacc[2 * kc][2],     sacc[2 * kc][3],     ph[1], pl[1]);
            split2(sacc[2 * kc + 1][0], sacc[2 * kc + 1][1], ph[2], pl[2]);
            split2(sacc[2 * kc + 1][2], sacc[2 * kc + 1][3], ph[3], pl[3]);
            #pragma unroll
            for (int ntp = 0; ntp < 4; ntp++) {
                uint32_t vh[4], vl[4];
                uint32_t voff = (uint32_t)(kc * 16 + (m_ & 1) * 8 + r_) * APB
                              + (uint32_t)(ntp * 16 + ((m_ >> 1) & 1) * 8) * 2;
                LDSM4T(vh, st + OFF_VHI + voff);
                LDSM4T(vl, st + OFF_VLO + voff);
                MMA16816(oacc[2 * ntp],     ph, vh[0], vh[1]);
                MMA16816(oacc[2 * ntp],     ph, vl[0], vl[1]);
                MMA16816(oacc[2 * ntp],     pl, vh[0], vh[1]);
                MMA16816(oacc[2 * ntp + 1], ph, vh[2], vh[3]);
                MMA16816(oacc[2 * ntp + 1], ph, vl[2], vl[3]);
                MMA16816(oacc[2 * ntp + 1], pl, vh[2], vh[3]);
            }
        }

        __syncthreads();                      // done reading buf (i&1)
        if (i + 2 < NKV) {
            load_kv(i + 2, i & 1);
            asm volatile("cp.async.commit_group;");
        }
        if (i + 1 < NKV) {
            if (i + 2 < NKV) asm volatile("cp.async.wait_group 1;" ::: "memory");
            else             asm volatile("cp.async.wait_group 0;" ::: "memory");
            __syncthreads();
        }
    }

    // ---- epilogue: ctx hi/lo bf16, layout [b*N + n][h*64 + d] ----
    float inv0 = 1.f / l_run[0], inv1 = 1.f / l_run[1];
    int rg0 = q0 + wid * 16 + (lane >> 2);
    int rg1 = rg0 + 8;
    int Cb = h * 64 + (lane & 3) * 2;
    #pragma unroll
    for (int nt = 0; nt < 8; nt++) {
        int C = Cb + nt * 8;
        if (rg0 < NTOK) {
            uint32_t hi, lo;
            split2(oacc[nt][0] * inv0, oacc[nt][1] * inv0, hi, lo);
            size_t idx = (size_t)(b * NTOK + rg0) * DMODEL + C;
            *(uint32_t*)&g_chi[idx] = hi;
            *(uint32_t*)&g_clo[idx] = lo;
        }
        if (rg1 < NTOK) {
            uint32_t hi, lo;
            split2(oacc[nt][2] * inv1, oacc[nt][3] * inv1, hi, lo);
            size_t idx = (size_t)(b * NTOK + rg1) * DMODEL + C;
            *(uint32_t*)&g_chi[idx] = hi;
            *(uint32_t*)&g_clo[idx] = lo;
        }
    }
}

// ---------------------------------------------------------------------------
extern "C" void kernel_launch(void* const* d_in, const int* in_sizes, int n_in,
                              void* d_out, int out_size)
{
    const float* hs   = (const float*)d_in[0];
    const float* sinp = (const float*)d_in[1];
    const float* cosp = (const float*)d_in[2];
    const float* Wq   = (const float*)d_in[3];
    const float* bq   = (const float*)d_in[4];
    const float* Wk   = (const float*)d_in[5];
    const float* bk   = (const float*)d_in[6];
    const float* Wv   = (const float*)d_in[7];
    const float* bv   = (const float*)d_in[8];
    const float* Wo   = (const float*)d_in[9];
    const float* bo   = (const float*)d_in[10];
    float* out = (float*)d_out;

    cudaFuncSetAttribute(wm_gemm_kernel,
                         cudaFuncAttributeMaxDynamicSharedMemorySize, GSM_BYTES);
    cudaFuncSetAttribute(attn_tc_kernel,
                         cudaFuncAttributeMaxDynamicSharedMemorySize, ATT_SMEM);

    split_x_kernel<<<(BNROWS * DMODEL) / 256, 256>>>(hs);
    split_w_kernel<<<(4 * DMODEL * DMODEL) / 256, 256>>>(Wq, Wk, Wv, Wo);
    biaspack_kernel<<<12, 256>>>(bq, bk, bv);

    wm_gemm_kernel<<<dim3(3 * DMODEL / 128, (BNROWS + 127) / 128), 256, GSM_BYTES>>>(
        bo, out, 1);

    prep_kernel<<<(3 * BATCH * NHEAD * NTOK * 32) / 256, 256>>>(sinp, cosp);

    attn_tc_kernel<<<dim3((NTOK + 127) / 128, NHEAD, BATCH), 256, ATT_SMEM>>>();

    wm_gemm_kernel<<<dim3(DMODEL / 128, (BNROWS + 127) / 128), 256, GSM_BYTES>>>(
        bo, out, 0);
}

// round 5
// speedup vs baseline: 3.7312x; 1.2145x over previous
#include <cuda_runtime.h>
#include <cuda_bf16.h>
#include <cuda_fp16.h>
#include <cstdint>

#define BATCH  16
#define NTOK   1029
#define NHEAD  16
#define HDIM   64
#define DMODEL 1024
#define PREFIX 5
#define BNROWS (BATCH * NTOK)   // 16464
#define BHN    (BATCH * NHEAD * NTOK)

// ---------------- scratch ----------------
__device__ float g_q[BHN * HDIM];
__device__ float g_k[BHN * HDIM];
__device__ float g_v[BHN * HDIM];

__device__ __half g_xhi[BNROWS * DMODEL];
__device__ __half g_xlo[BNROWS * DMODEL];
__device__ __half g_whi[3 * DMODEL * DMODEL];
__device__ __half g_wohi[DMODEL * DMODEL];
__device__ __half g_chi[BNROWS * DMODEL];
__device__ __half g_clo[BNROWS * DMODEL];
__device__ float g_bqkv[3 * DMODEL];

__device__ __nv_bfloat16 g_qhi[BHN * HDIM];
__device__ __nv_bfloat16 g_qlo[BHN * HDIM];
__device__ __nv_bfloat16 g_khi[BHN * HDIM];
__device__ __nv_bfloat16 g_klo[BHN * HDIM];
__device__ __nv_bfloat16 g_vhi[BHN * HDIM];
__device__ __nv_bfloat16 g_vlo[BHN * HDIM];

// ---------------- helpers ----------------
__device__ __forceinline__ uint32_t s2u(const void* p) {
    return (uint32_t)__cvta_generic_to_shared(p);
}
__device__ __forceinline__ void cp16(uint32_t d, const void* s, bool v) {
    asm volatile("cp.async.cg.shared.global [%0], [%1], 16, %2;"
                 :: "r"(d), "l"(s), "r"(v ? 16u : 0u));
}
#define LDSM4(r, addr) \
    asm volatile("ldmatrix.sync.aligned.m8n8.x4.shared.b16 {%0,%1,%2,%3}, [%4];" \
        : "=r"((r)[0]), "=r"((r)[1]), "=r"((r)[2]), "=r"((r)[3]) : "r"(addr))
#define LDSM4T(r, addr) \
    asm volatile("ldmatrix.sync.aligned.m8n8.x4.trans.shared.b16 {%0,%1,%2,%3}, [%4];" \
        : "=r"((r)[0]), "=r"((r)[1]), "=r"((r)[2]), "=r"((r)[3]) : "r"(addr))
#define MMABF(c, a, b0, b1) \
    asm volatile("mma.sync.aligned.m16n8k16.row.col.f32.bf16.bf16.f32 " \
        "{%0,%1,%2,%3}, {%4,%5,%6,%7}, {%8,%9}, {%0,%1,%2,%3};" \
        : "+f"((c)[0]), "+f"((c)[1]), "+f"((c)[2]), "+f"((c)[3]) \
        : "r"((a)[0]), "r"((a)[1]), "r"((a)[2]), "r"((a)[3]), "r"(b0), "r"(b1))
#define MMAFP(c, a, b0, b1) \
    asm volatile("mma.sync.aligned.m16n8k16.row.col.f32.f16.f16.f32 " \
        "{%0,%1,%2,%3}, {%4,%5,%6,%7}, {%8,%9}, {%0,%1,%2,%3};" \
        : "+f"((c)[0]), "+f"((c)[1]), "+f"((c)[2]), "+f"((c)[3]) \
        : "r"((a)[0]), "r"((a)[1]), "r"((a)[2]), "r"((a)[3]), "r"(b0), "r"(b1))

__device__ __forceinline__ void split2bf(float a, float b, uint32_t& hi, uint32_t& lo) {
    __nv_bfloat162 h = __floats2bfloat162_rn(a, b);
    float ra = a - __bfloat162float(h.x);
    float rb = b - __bfloat162float(h.y);
    __nv_bfloat162 l = __floats2bfloat162_rn(ra, rb);
    hi = *(uint32_t*)&h;
    lo = *(uint32_t*)&l;
}
__device__ __forceinline__ void split2h(float a, float b, uint32_t& hi, uint32_t& lo) {
    __half2 h = __floats2half2_rn(a, b);
    float ra = a - __low2float(h);
    float rb = b - __high2float(h);
    __half2 l = __floats2half2_rn(ra, rb);
    hi = *(uint32_t*)&h;
    lo = *(uint32_t*)&l;
}

// ---------------- conversion kernels ----------------
__global__ __launch_bounds__(256) void split_x_kernel(const float* __restrict__ in) {
    int i = blockIdx.x * 256 + threadIdx.x;
    float x = in[i];
    __half h = __float2half_rn(x);
    g_xhi[i] = h;
    g_xlo[i] = __float2half_rn(x - __half2float(h));
}
__global__ __launch_bounds__(256) void split_w_kernel(
    const float* __restrict__ Wq, const float* __restrict__ Wk,
    const float* __restrict__ Wv, const float* __restrict__ Wo) {
    int i = blockIdx.x * 256 + threadIdx.x;
    const int M1 = DMODEL * DMODEL;
    if (i < 3 * M1) {
        float x = (i < M1) ? Wq[i] : ((i < 2 * M1) ? Wk[i - M1] : Wv[i - 2 * M1]);
        g_whi[i] = __float2half_rn(x);
    } else {
        int j = i - 3 * M1;
        g_wohi[j] = __float2half_rn(Wo[j]);
    }
}
__global__ __launch_bounds__(256) void biaspack_kernel(
    const float* __restrict__ bq, const float* __restrict__ bk,
    const float* __restrict__ bv) {
    int i = blockIdx.x * 256 + threadIdx.x;
    if (i < 3 * DMODEL) {
        const float* s = (i < DMODEL) ? bq : ((i < 2 * DMODEL) ? bk : bv);
        g_bqkv[i] = s[i & (DMODEL - 1)];
    }
}

// ---------------- prep: RoPE + bf16 split of q,k,v ----------------
__global__ __launch_bounds__(256) void prep_kernel(
    const float* __restrict__ sinp, const float* __restrict__ cosp)
{
    int idx = blockIdx.x * 256 + threadIdx.x;
    const int per = BATCH * NHEAD * NTOK * 32;
    int t = idx / per;
    int r = idx - t * per;
    int d = r & 31;
    int rowi = r >> 5;
    int n = rowi % NTOK;

    const float* src = (t == 0) ? g_q : ((t == 1) ? g_k : g_v);
    __nv_bfloat16* dhi = (t == 0) ? g_qhi : ((t == 1) ? g_khi : g_vhi);
    __nv_bfloat16* dlo = (t == 0) ? g_qlo : ((t == 1) ? g_klo : g_vlo);

    size_t base = (size_t)rowi * 64;
    float x1 = src[base + d], x2 = src[base + d + 32];
    float y1 = x1, y2 = x2;
    if (t < 2 && n >= PREFIX) {
        int pos = n - PREFIX;
        float c1 = cosp[pos * 64 + d],      s1 = sinp[pos * 64 + d];
        float c2 = cosp[pos * 64 + d + 32], s2 = sinp[pos * 64 + d + 32];
        y1 = x1 * c1 - x2 * s1;
        y2 = x2 * c2 + x1 * s2;
    }
    __nv_bfloat16 h1 = __float2bfloat16(y1);
    __nv_bfloat16 h2 = __float2bfloat16(y2);
    dhi[base + d]      = h1;
    dhi[base + d + 32] = h2;
    dlo[base + d]      = __float2bfloat16(y1 - __bfloat162float(h1));
    dlo[base + d + 32] = __float2bfloat16(y2 - __bfloat162float(h2));
}

// ---------------- warp-MMA fp16-split GEMM (2 MMAs per tile) ----------------
// C[M,N] = A[M,K] @ B[N,K]^T (+bias). A = Ahi+Alo (fp16 exact), B = Bhi (fp16).
// CTA 128x128, BK=32, 3-stage cp.async pipeline, one barrier per K-iter.
#define BK 32
#define NKIT (DMODEL / BK)          // 32
#define SROWB 80
#define BUFB  (128 * SROWB)         // 10240
#define STAGEB (3 * BUFB)           // 30720 (Ahi|Alo|Bhi)
#define GSM_BYTES (3 * STAGEB)      // 92160

__global__ __launch_bounds__(256) void wm_gemm_kernel(
    const float* __restrict__ bias_out, float* __restrict__ outp, int qkv_mode)
{
    extern __shared__ char sm[];
    const uint32_t sb = s2u(sm);
    const int tid = threadIdx.x;
    const int wid = tid >> 5, lane = tid & 31;
    const int warp_m = wid & 1, warp_n = wid >> 1;
    const int row0 = blockIdx.y * 128;
    const int col0 = blockIdx.x * 128;

    const __half* Ahi = qkv_mode ? g_xhi : g_chi;
    const __half* Alo = qkv_mode ? g_xlo : g_clo;
    const __half* Bh  = qkv_mode ? g_whi : g_wohi;

    float acc[4][4][4] = {};

    // 1536 16B-chunks per stage (3 mats x 512), 6 per thread
    auto load_stage = [&](int kt, int buf) {
        const size_t kb = (size_t)kt * (BK * 2);
        const uint32_t s0 = sb + buf * STAGEB;
        #pragma unroll
        for (int t = 0; t < 6; t++) {
            int chunk = tid + t * 256;
            int mat = chunk >> 9, rem = chunk & 511;
            int r = rem >> 2, c = rem & 3;
            uint32_t so = (uint32_t)mat * BUFB + r * SROWB + c * 16;
            if (mat < 2) {
                int ga = row0 + r;
                bool av = ga < BNROWS;
                size_t go = (size_t)(av ? ga : 0) * (DMODEL * 2) + kb + c * 16;
                const char* src = mat ? (const char*)Alo : (const char*)Ahi;
                cp16(s0 + so, src + go, av);
            } else {
                size_t go = (size_t)(col0 + r) * (DMODEL * 2) + kb + c * 16;
                cp16(s0 + so, (const char*)Bh + go, true);
            }
        }
        asm volatile("cp.async.commit_group;");
    };

    load_stage(0, 0);
    load_stage(1, 1);

    const int a_row = warp_m * 64 + (lane & 15);
    const int a_colsel = (lane >> 4) << 3;
    const int b_row = warp_n * 32 + ((lane >> 4) & 1) * 8 + (lane & 7);
    const int b_colsel = ((lane >> 3) & 1) << 3;

    for (int kt = 0; kt < NKIT; kt++) {
        if (kt + 1 < NKIT) asm volatile("cp.async.wait_group 1;" ::: "memory");
        else               asm volatile("cp.async.wait_group 0;" ::: "memory");
        __syncthreads();
        if (kt + 2 < NKIT) load_stage(kt + 2, (kt + 2) % 3);

        const uint32_t s0 = sb + (kt % 3) * STAGEB;
        const uint32_t sA_hi = s0;
        const uint32_t sA_lo = s0 + BUFB;
        const uint32_t sB    = s0 + 2 * BUFB;

        #pragma unroll
        for (int kk = 0; kk < BK; kk += 16) {
            uint32_t ah[4][4], al[4][4], bh[2][4];
            #pragma unroll
            for (int mt = 0; mt < 4; mt++) {
                uint32_t off = (uint32_t)(a_row + mt * 16) * SROWB
                             + (uint32_t)(kk + a_colsel) * 2;
                LDSM4(ah[mt], sA_hi + off);
                LDSM4(al[mt], sA_lo + off);
            }
            #pragma unroll
            for (int p = 0; p < 2; p++) {
                uint32_t off = (uint32_t)(b_row + p * 16) * SROWB
                             + (uint32_t)(kk + b_colsel) * 2;
                LDSM4(bh[p], sB + off);
            }
            #pragma unroll
            for (int mt = 0; mt < 4; mt++)
                #pragma unroll
                for (int nt = 0; nt < 4; nt++) {
                    int p = nt >> 1, q = (nt & 1) * 2;
                    MMAFP(acc[mt][nt], ah[mt], bh[p][q], bh[p][q + 1]);
                    MMAFP(acc[mt][nt], al[mt], bh[p][q], bh[p][q + 1]);
                }
        }
    }

    const int crow = row0 + warp_m * 64 + (lane >> 2);
    const int ccol = col0 + warp_n * 32 + (lane & 3) * 2;
    #pragma unroll
    for (int mt = 0; mt < 4; mt++) {
        #pragma unroll
        for (int rr = 0; rr < 2; rr++) {
            int R = crow + mt * 16 + rr * 8;
            if (R >= BNROWS) continue;
            int b_ = R / NTOK, n = R - b_ * NTOK;
            #pragma unroll
            for (int nt = 0; nt < 4; nt++) {
                float v0 = acc[mt][nt][rr * 2 + 0];
                float v1 = acc[mt][nt][rr * 2 + 1];
                int C = ccol + nt * 8;
                if (qkv_mode) {
                    #pragma unroll
                    for (int e = 0; e < 2; e++) {
                        int Ce = C + e;
                        float val = (e ? v1 : v0) + g_bqkv[Ce];
                        int wsel = Ce >> 10, cl = Ce & 1023, h = cl >> 6, d = cl & 63;
                        float* dst = (wsel == 0) ? g_q : ((wsel == 1) ? g_k : g_v);
                        dst[(size_t)((b_ * NHEAD + h) * NTOK + n) * 64 + d] = val;
                    }
                } else {
                    outp[(size_t)R * DMODEL + C]     = v0 + bias_out[C];
                    outp[(size_t)R * DMODEL + C + 1] = v1 + bias_out[C + 1];
                }
            }
        }
    }
}

// ---------------- tensor-core flash attention (bf16 3-term, as R4) ----------------
#define APB 144
#define SM_QHI 0
#define SM_QLO (128 * APB)
#define SM_ST0 (2 * 128 * APB)
#define STG_SZ (4 * 64 * APB)
#define OFF_KHI 0
#define OFF_KLO (64 * APB)
#define OFF_VHI (2 * 64 * APB)
#define OFF_VLO (3 * 64 * APB)
#define ATT_SMEM (SM_ST0 + 2 * STG_SZ)
#define NKV 17

__global__ __launch_bounds__(256, 2) void attn_tc_kernel()
{
    extern __shared__ char sm[];
    const uint32_t sb = s2u(sm);
    const int tid = threadIdx.x;
    const int wid = tid >> 5, lane = tid & 31;
    const int b = blockIdx.z, h = blockIdx.y;
    const int q0 = blockIdx.x * 128;
    const size_t base = (size_t)(b * NHEAD + h) * NTOK;

    {
        #pragma unroll
        for (int t = 0; t < 8; t++) {
            int chunk = tid + t * 256;
            int mq = chunk >> 10, rem = chunk & 1023;
            int r = rem >> 3, c = rem & 7;
            int gr = q0 + r;
            bool v = gr < NTOK;
            size_t go = (base + (v ? gr : 0)) * 128 + c * 16;
            const char* src = mq ? (const char*)g_qlo : (const char*)g_qhi;
            cp16(sb + (mq ? SM_QLO : SM_QHI) + r * APB + c * 16, src + go, v);
        }
    }
    auto load_kv = [&](int i, int buf) {
        int k0 = i * 64;
        #pragma unroll
        for (int t = 0; t < 8; t++) {
            int chunk = tid + t * 256;
            int mat = chunk >> 9, rem = chunk & 511;
            int r = rem >> 3, c = rem & 7;
            int gr = k0 + r;
            bool v = gr < NTOK;
            size_t go = (base + (v ? gr : 0)) * 128 + c * 16;
            const char* src = (mat == 0) ? (const char*)g_khi
                            : (mat == 1) ? (const char*)g_klo
                            : (mat == 2) ? (const char*)g_vhi
                                         : (const char*)g_vlo;
            cp16(sb + SM_ST0 + buf * STG_SZ + mat * (64 * APB) + r * APB + c * 16,
                 src + go, v);
        }
    };
    load_kv(0, 0);
    asm volatile("cp.async.commit_group;");
    load_kv(1, 1);
    asm volatile("cp.async.commit_group;");
    asm volatile("cp.async.wait_group 1;" ::: "memory");
    __syncthreads();

    float oacc[8][4] = {};
    float m_run[2] = {-1e30f, -1e30f};
    float l_run[2] = {0.f, 0.f};

    const int la_row = lane & 15, la_cs = (lane >> 4) * 16;
    const int m_ = lane >> 3, r_ = lane & 7;

    for (int i = 0; i < NKV; i++) {
        const uint32_t st = sb + SM_ST0 + (i & 1) * STG_SZ;
        const int k0 = i * 64;

        float sacc[8][4] = {};
        #pragma unroll
        for (int ks = 0; ks < 4; ks++) {
            uint32_t qh[4], ql[4];
            uint32_t qoff = (uint32_t)(wid * 16 + la_row) * APB + (uint32_t)(ks * 32 + la_cs);
            LDSM4(qh, sb + SM_QHI + qoff);
            LDSM4(ql, sb + SM_QLO + qoff);
            #pragma unroll
            for (int ntp = 0; ntp < 4; ntp++) {
                uint32_t kh[4], kl[4];
                uint32_t koff = (uint32_t)(ntp * 16 + ((m_ >> 1) & 1) * 8 + r_) * APB
                              + (uint32_t)(ks * 32 + (m_ & 1) * 16);
                LDSM4(kh, st + OFF_KHI + koff);
                LDSM4(kl, st + OFF_KLO + koff);
                MMABF(sacc[2 * ntp],     qh, kh[0], kh[1]);
                MMABF(sacc[2 * ntp],     qh, kl[0], kl[1]);
                MMABF(sacc[2 * ntp],     ql, kh[0], kh[1]);
                MMABF(sacc[2 * ntp + 1], qh, kh[2], kh[3]);
                MMABF(sacc[2 * ntp + 1], qh, kl[2], kl[3]);
                MMABF(sacc[2 * ntp + 1], ql, kh[2], kh[3]);
            }
        }

        float tm0 = -1e30f, tm1 = -1e30f;
        #pragma unroll
        for (int nt = 0; nt < 8; nt++) {
            int cbase = k0 + nt * 8 + (lane & 3) * 2;
            #pragma unroll
            for (int e = 0; e < 4; e++) {
                float sv = sacc[nt][e] * 0.125f;
                if (cbase + (e & 1) >= NTOK) sv = -1e30f;
                sacc[nt][e] = sv;
            }
            tm0 = fmaxf(tm0, fmaxf(sacc[nt][0], sacc[nt][1]));
            tm1 = fmaxf(tm1, fmaxf(sacc[nt][2], sacc[nt][3]));
        }
        tm0 = fmaxf(tm0, __shfl_xor_sync(0xffffffffu, tm0, 1));
        tm0 = fmaxf(tm0, __shfl_xor_sync(0xffffffffu, tm0, 2));
        tm1 = fmaxf(tm1, __shfl_xor_sync(0xffffffffu, tm1, 1));
        tm1 = fmaxf(tm1, __shfl_xor_sync(0xffffffffu, tm1, 2));
        float mn0 = fmaxf(m_run[0], tm0), mn1 = fmaxf(m_run[1], tm1);
        float al0 = __expf(m_run[0] - mn0), al1 = __expf(m_run[1] - mn1);
        m_run[0] = mn0; m_run[1] = mn1;

        float rs0 = 0.f, rs1 = 0.f;
        #pragma unroll
        for (int nt = 0; nt < 8; nt++) {
            sacc[nt][0] = __expf(sacc[nt][0] - mn0);
            sacc[nt][1] = __expf(sacc[nt][1] - mn0);
            sacc[nt][2] = __expf(sacc[nt][2] - mn1);
            sacc[nt][3] = __expf(sacc[nt][3] - mn1);
            rs0 += sacc[nt][0] + sacc[nt][1];
            rs1 += sacc[nt][2] + sacc[nt][3];
        }
        rs0 += __shfl_xor_sync(0xffffffffu, rs0, 1);
        rs0 += __shfl_xor_sync(0xffffffffu, rs0, 2);
        rs1 += __shfl_xor_sync(0xffffffffu, rs1, 1);
        rs1 += __shfl_xor_sync(0xffffffffu, rs1, 2);
        l_run[0] = l_run[0] * al0 + rs0;
        l_run[1] = l_run[1] * al1 + rs1;
        #pragma unroll
        for (int nt = 0; nt < 8; nt++) {
            oacc[nt][0] *= al0; oacc[nt][1] *= al0;
            oacc[nt][2] *= al1; oacc[nt][3] *= al1;
        }

        #pragma unroll
        for (int kc = 0; kc < 4; kc++) {
            uint32_t ph[4], pl[4];
            split2bf(sacc[2 * kc][0],     sacc[2 * kc][1],     ph[0], pl[0]);
            split2bf(sacc[2 * kc][2],     sacc[2 * kc][3],     ph[1], pl[1]);
            split2bf(sacc[2 * kc + 1][0], sacc[2 * kc + 1][1], ph[2], pl[2]);
            split2bf(sacc[2 * kc + 1][2], sacc[2 * kc + 1][3], ph[3], pl[3]);
            #pragma unroll
            for (int ntp = 0; ntp < 4; ntp++) {
                uint32_t vh[4], vl[4];
                uint32_t voff = (uint32_t)(kc * 16 + (m_ & 1) * 8 + r_) * APB
                              + (uint32_t)(ntp * 16 + ((m_ >> 1) & 1) * 8) * 2;
                LDSM4T(vh, st + OFF_VHI + voff);
                LDSM4T(vl, st + OFF_VLO + voff);
                MMABF(oacc[2 * ntp],     ph, vh[0], vh[1]);
                MMABF(oacc[2 * ntp],     ph, vl[0], vl[1]);
                MMABF(oacc[2 * ntp],     pl, vh[0], vh[1]);
                MMABF(oacc[2 * ntp + 1], ph, vh[2], vh[3]);
                MMABF(oacc[2 * ntp + 1], ph, vl[2], vl[3]);
                MMABF(oacc[2 * ntp + 1], pl, vh[2], vh[3]);
            }
        }

        __syncthreads();
        if (i + 2 < NKV) {
            load_kv(i + 2, i & 1);
            asm volatile("cp.async.commit_group;");
        }
        if (i + 1 < NKV) {
            if (i + 2 < NKV) asm volatile("cp.async.wait_group 1;" ::: "memory");
            else             asm volatile("cp.async.wait_group 0;" ::: "memory");
            __syncthreads();
        }
    }

    float inv0 = 1.f / l_run[0], inv1 = 1.f / l_run[1];
    int rg0 = q0 + wid * 16 + (lane >> 2);
    int rg1 = rg0 + 8;
    int Cb = h * 64 + (lane & 3) * 2;
    #pragma unroll
    for (int nt = 0; nt < 8; nt++) {
        int C = Cb + nt * 8;
        if (rg0 < NTOK) {
            uint32_t hi, lo;
            split2h(oacc[nt][0] * inv0, oacc[nt][1] * inv0, hi, lo);
            size_t idx = (size_t)(b * NTOK + rg0) * DMODEL + C;
            *(uint32_t*)&g_chi[idx] = hi;
            *(uint32_t*)&g_clo[idx] = lo;
        }
        if (rg1 < NTOK) {
            uint32_t hi, lo;
            split2h(oacc[nt][2] * inv1, oacc[nt][3] * inv1, hi, lo);
            size_t idx = (size_t)(b * NTOK + rg1) * DMODEL + C;
            *(uint32_t*)&g_chi[idx] = hi;
            *(uint32_t*)&g_clo[idx] = lo;
        }
    }
}

// ---------------------------------------------------------------------------
extern "C" void kernel_launch(void* const* d_in, const int* in_sizes, int n_in,
                              void* d_out, int out_size)
{
    const float* hs   = (const float*)d_in[0];
    const float* sinp = (const float*)d_in[1];
    const float* cosp = (const float*)d_in[2];
    const float* Wq   = (const float*)d_in[3];
    const float* bq   = (const float*)d_in[4];
    const float* Wk   = (const float*)d_in[5];
    const float* bk   = (const float*)d_in[6];
    const float* Wv   = (const float*)d_in[7];
    const float* bv   = (const float*)d_in[8];
    const float* Wo   = (const float*)d_in[9];
    const float* bo   = (const float*)d_in[10];
    float* out = (float*)d_out;

    cudaFuncSetAttribute(wm_gemm_kernel,
                         cudaFuncAttributeMaxDynamicSharedMemorySize, GSM_BYTES);
    cudaFuncSetAttribute(attn_tc_kernel,
                         cudaFuncAttributeMaxDynamicSharedMemorySize, ATT_SMEM);

    split_x_kernel<<<(BNROWS * DMODEL) / 256, 256>>>(hs);
    split_w_kernel<<<(4 * DMODEL * DMODEL) / 256, 256>>>(Wq, Wk, Wv, Wo);
    biaspack_kernel<<<12, 256>>>(bq, bk, bv);

    wm_gemm_kernel<<<dim3(3 * DMODEL / 128, (BNROWS + 127) / 128), 256, GSM_BYTES>>>(
        bo, out, 1);

    prep_kernel<<<(3 * BATCH * NHEAD * NTOK * 32) / 256, 256>>>(sinp, cosp);

    attn_tc_kernel<<<dim3((NTOK + 127) / 128, NHEAD, BATCH), 256, ATT_SMEM>>>();

    wm_gemm_kernel<<<dim3(DMODEL / 128, (BNROWS + 127) / 128), 256, GSM_BYTES>>>(
        bo, out, 0);
}

// round 6
// speedup vs baseline: 4.1958x; 1.1245x over previous
#include <cuda_runtime.h>
#include <cuda_bf16.h>
#include <cuda_fp16.h>
#include <cstdint>

#define BATCH  16
#define NTOK   1029
#define NHEAD  16
#define HDIM   64
#define DMODEL 1024
#define PREFIX 5
#define BNROWS (BATCH * NTOK)   // 16464
#define BHN    (BATCH * NHEAD * NTOK)

// ---------------- scratch ----------------
__device__ float g_q[BHN * HDIM];
__device__ float g_k[BHN * HDIM];
__device__ float g_v[BHN * HDIM];

__device__ __half g_xhi[BNROWS * DMODEL];
__device__ __half g_xlo[BNROWS * DMODEL];
__device__ __half g_whi[3 * DMODEL * DMODEL];
__device__ __half g_wohi[DMODEL * DMODEL];
__device__ __half g_chi[BNROWS * DMODEL];
__device__ __half g_clo[BNROWS * DMODEL];
__device__ float g_bqkv[3 * DMODEL];

__device__ __half g_qhi[BHN * HDIM];   // RoPE'd, pre-scaled by 0.125, hi
__device__ __half g_qlo[BHN * HDIM];   // lo term (exact-ish split)
__device__ __half g_kh [BHN * HDIM];   // RoPE'd, single fp16
__device__ __half g_vh [BHN * HDIM];   // single fp16

// ---------------- helpers ----------------
__device__ __forceinline__ uint32_t s2u(const void* p) {
    return (uint32_t)__cvta_generic_to_shared(p);
}
__device__ __forceinline__ void cp16(uint32_t d, const void* s, bool v) {
    asm volatile("cp.async.cg.shared.global [%0], [%1], 16, %2;"
                 :: "r"(d), "l"(s), "r"(v ? 16u : 0u));
}
#define LDSM4(r, addr) \
    asm volatile("ldmatrix.sync.aligned.m8n8.x4.shared.b16 {%0,%1,%2,%3}, [%4];" \
        : "=r"((r)[0]), "=r"((r)[1]), "=r"((r)[2]), "=r"((r)[3]) : "r"(addr))
#define LDSM4T(r, addr) \
    asm volatile("ldmatrix.sync.aligned.m8n8.x4.trans.shared.b16 {%0,%1,%2,%3}, [%4];" \
        : "=r"((r)[0]), "=r"((r)[1]), "=r"((r)[2]), "=r"((r)[3]) : "r"(addr))
#define MMAFP(c, a, b0, b1) \
    asm volatile("mma.sync.aligned.m16n8k16.row.col.f32.f16.f16.f32 " \
        "{%0,%1,%2,%3}, {%4,%5,%6,%7}, {%8,%9}, {%0,%1,%2,%3};" \
        : "+f"((c)[0]), "+f"((c)[1]), "+f"((c)[2]), "+f"((c)[3]) \
        : "r"((a)[0]), "r"((a)[1]), "r"((a)[2]), "r"((a)[3]), "r"(b0), "r"(b1))

__device__ __forceinline__ void split2h(float a, float b, uint32_t& hi, uint32_t& lo) {
    __half2 h = __floats2half2_rn(a, b);
    float ra = a - __low2float(h);
    float rb = b - __high2float(h);
    __half2 l = __floats2half2_rn(ra, rb);
    hi = *(uint32_t*)&h;
    lo = *(uint32_t*)&l;
}

// ---------------- conversion kernels ----------------
__global__ __launch_bounds__(256) void split_x_kernel(const float* __restrict__ in) {
    int i = blockIdx.x * 256 + threadIdx.x;
    float x = in[i];
    __half h = __float2half_rn(x);
    g_xhi[i] = h;
    g_xlo[i] = __float2half_rn(x - __half2float(h));
}
__global__ __launch_bounds__(256) void split_w_kernel(
    const float* __restrict__ Wq, const float* __restrict__ Wk,
    const float* __restrict__ Wv, const float* __restrict__ Wo) {
    int i = blockIdx.x * 256 + threadIdx.x;
    const int M1 = DMODEL * DMODEL;
    if (i < 3 * M1) {
        float x = (i < M1) ? Wq[i] : ((i < 2 * M1) ? Wk[i - M1] : Wv[i - 2 * M1]);
        g_whi[i] = __float2half_rn(x);
    } else {
        int j = i - 3 * M1;
        g_wohi[j] = __float2half_rn(Wo[j]);
    }
}
__global__ __launch_bounds__(256) void biaspack_kernel(
    const float* __restrict__ bq, const float* __restrict__ bk,
    const float* __restrict__ bv) {
    int i = blockIdx.x * 256 + threadIdx.x;
    if (i < 3 * DMODEL) {
        const float* s = (i < DMODEL) ? bq : ((i < 2 * DMODEL) ? bk : bv);
        g_bqkv[i] = s[i & (DMODEL - 1)];
    }
}

// ---------------- prep: RoPE + fp16 pack of q,k,v ----------------
// q: RoPE, *0.125, split hi/lo.  k: RoPE, single fp16.  v: single fp16.
__global__ __launch_bounds__(256) void prep_kernel(
    const float* __restrict__ sinp, const float* __restrict__ cosp)
{
    int idx = blockIdx.x * 256 + threadIdx.x;
    const int per = BATCH * NHEAD * NTOK * 32;
    int t = idx / per;
    int r = idx - t * per;
    int d = r & 31;
    int rowi = r >> 5;
    int n = rowi % NTOK;

    const float* src = (t == 0) ? g_q : ((t == 1) ? g_k : g_v);
    size_t base = (size_t)rowi * 64;
    float x1 = src[base + d], x2 = src[base + d + 32];
    float y1 = x1, y2 = x2;
    if (t < 2 && n >= PREFIX) {
        int pos = n - PREFIX;
        float c1 = cosp[pos * 64 + d],      s1 = sinp[pos * 64 + d];
        float c2 = cosp[pos * 64 + d + 32], s2 = sinp[pos * 64 + d + 32];
        y1 = x1 * c1 - x2 * s1;
        y2 = x2 * c2 + x1 * s2;
    }
    if (t == 0) {
        y1 *= 0.125f; y2 *= 0.125f;
        __half h1 = __float2half_rn(y1), h2 = __float2half_rn(y2);
        g_qhi[base + d]      = h1;
        g_qhi[base + d + 32] = h2;
        g_qlo[base + d]      = __float2half_rn(y1 - __half2float(h1));
        g_qlo[base + d + 32] = __float2half_rn(y2 - __half2float(h2));
    } else if (t == 1) {
        g_kh[base + d]      = __float2half_rn(y1);
        g_kh[base + d + 32] = __float2half_rn(y2);
    } else {
        g_vh[base + d]      = __float2half_rn(y1);
        g_vh[base + d + 32] = __float2half_rn(y2);
    }
}

// ---------------- warp-MMA fp16-split GEMM (unchanged from R5) ----------------
#define BK 32
#define NKIT (DMODEL / BK)
#define SROWB 80
#define BUFB  (128 * SROWB)
#define STAGEB (3 * BUFB)
#define GSM_BYTES (3 * STAGEB)

__global__ __launch_bounds__(256) void wm_gemm_kernel(
    const float* __restrict__ bias_out, float* __restrict__ outp, int qkv_mode)
{
    extern __shared__ char sm[];
    const uint32_t sb = s2u(sm);
    const int tid = threadIdx.x;
    const int wid = tid >> 5, lane = tid & 31;
    const int warp_m = wid & 1, warp_n = wid >> 1;
    const int row0 = blockIdx.y * 128;
    const int col0 = blockIdx.x * 128;

    const __half* Ahi = qkv_mode ? g_xhi : g_chi;
    const __half* Alo = qkv_mode ? g_xlo : g_clo;
    const __half* Bh  = qkv_mode ? g_whi : g_wohi;

    float acc[4][4][4] = {};

    auto load_stage = [&](int kt, int buf) {
        const size_t kb = (size_t)kt * (BK * 2);
        const uint32_t s0 = sb + buf * STAGEB;
        #pragma unroll
        for (int t = 0; t < 6; t++) {
            int chunk = tid + t * 256;
            int mat = chunk >> 9, rem = chunk & 511;
            int r = rem >> 2, c = rem & 3;
            uint32_t so = (uint32_t)mat * BUFB + r * SROWB + c * 16;
            if (mat < 2) {
                int ga = row0 + r;
                bool av = ga < BNROWS;
                size_t go = (size_t)(av ? ga : 0) * (DMODEL * 2) + kb + c * 16;
                const char* src = mat ? (const char*)Alo : (const char*)Ahi;
                cp16(s0 + so, src + go, av);
            } else {
                size_t go = (size_t)(col0 + r) * (DMODEL * 2) + kb + c * 16;
                cp16(s0 + so, (const char*)Bh + go, true);
            }
        }
        asm volatile("cp.async.commit_group;");
    };

    load_stage(0, 0);
    load_stage(1, 1);

    const int a_row = warp_m * 64 + (lane & 15);
    const int a_colsel = (lane >> 4) << 3;
    const int b_row = warp_n * 32 + ((lane >> 4) & 1) * 8 + (lane & 7);
    const int b_colsel = ((lane >> 3) & 1) << 3;

    for (int kt = 0; kt < NKIT; kt++) {
        if (kt + 1 < NKIT) asm volatile("cp.async.wait_group 1;" ::: "memory");
        else               asm volatile("cp.async.wait_group 0;" ::: "memory");
        __syncthreads();
        if (kt + 2 < NKIT) load_stage(kt + 2, (kt + 2) % 3);

        const uint32_t s0 = sb + (kt % 3) * STAGEB;
        const uint32_t sA_hi = s0;
        const uint32_t sA_lo = s0 + BUFB;
        const uint32_t sB    = s0 + 2 * BUFB;

        #pragma unroll
        for (int kk = 0; kk < BK; kk += 16) {
            uint32_t ah[4][4], al[4][4], bh[2][4];
            #pragma unroll
            for (int mt = 0; mt < 4; mt++) {
                uint32_t off = (uint32_t)(a_row + mt * 16) * SROWB
                             + (uint32_t)(kk + a_colsel) * 2;
                LDSM4(ah[mt], sA_hi + off);
                LDSM4(al[mt], sA_lo + off);
            }
            #pragma unroll
            for (int p = 0; p < 2; p++) {
                uint32_t off = (uint32_t)(b_row + p * 16) * SROWB
                             + (uint32_t)(kk + b_colsel) * 2;
                LDSM4(bh[p], sB + off);
            }
            #pragma unroll
            for (int mt = 0; mt < 4; mt++)
                #pragma unroll
                for (int nt = 0; nt < 4; nt++) {
                    int p = nt >> 1, q = (nt & 1) * 2;
                    MMAFP(acc[mt][nt], ah[mt], bh[p][q], bh[p][q + 1]);
                    MMAFP(acc[mt][nt], al[mt], bh[p][q], bh[p][q + 1]);
                }
        }
    }

    const int crow = row0 + warp_m * 64 + (lane >> 2);
    const int ccol = col0 + warp_n * 32 + (lane & 3) * 2;
    #pragma unroll
    for (int mt = 0; mt < 4; mt++) {
        #pragma unroll
        for (int rr = 0; rr < 2; rr++) {
            int R = crow + mt * 16 + rr * 8;
            if (R >= BNROWS) continue;
            int b_ = R / NTOK, n = R - b_ * NTOK;
            #pragma unroll
            for (int nt = 0; nt < 4; nt++) {
                float v0 = acc[mt][nt][rr * 2 + 0];
                float v1 = acc[mt][nt][rr * 2 + 1];
                int C = ccol + nt * 8;
                if (qkv_mode) {
                    #pragma unroll
                    for (int e = 0; e < 2; e++) {
                        int Ce = C + e;
                        float val = (e ? v1 : v0) + g_bqkv[Ce];
                        int wsel = Ce >> 10, cl = Ce & 1023, h = cl >> 6, d = cl & 63;
                        float* dst = (wsel == 0) ? g_q : ((wsel == 1) ? g_k : g_v);
                        dst[(size_t)((b_ * NHEAD + h) * NTOK + n) * 64 + d] = val;
                    }
                } else {
                    outp[(size_t)R * DMODEL + C]     = v0 + bias_out[C];
                    outp[(size_t)R * DMODEL + C + 1] = v1 + bias_out[C + 1];
                }
            }
        }
    }
}

// ---------------- tensor-core flash attention (fp16 2-term) ----------------
// Q split hi/lo (pre-scaled), K and V single fp16. 4 MMAs per (ks|kc, ntp).
#define APB 144
#define SM_QHI 0
#define SM_QLO (128 * APB)            // 18432
#define SM_ST0 (2 * 128 * APB)        // 36864
#define STG_SZ (2 * 64 * APB)         // 18432 (k|v)
#define OFF_K 0
#define OFF_V (64 * APB)
#define ATT_SMEM (SM_ST0 + 2 * STG_SZ)  // 73728
#define NKV 17

__global__ __launch_bounds__(256, 3) void attn_tc_kernel()
{
    extern __shared__ char sm[];
    const uint32_t sb = s2u(sm);
    const int tid = threadIdx.x;
    const int wid = tid >> 5, lane = tid & 31;
    const int b = blockIdx.z, h = blockIdx.y;
    const int q0 = blockIdx.x * 128;
    const size_t base = (size_t)(b * NHEAD + h) * NTOK;

    // Q load: 2048 chunks (hi 1024 | lo 1024), 8 per thread
    {
        #pragma unroll
        for (int t = 0; t < 8; t++) {
            int chunk = tid + t * 256;
            int mq = chunk >> 10, rem = chunk & 1023;
            int r = rem >> 3, c = rem & 7;
            int gr = q0 + r;
            bool v = gr < NTOK;
            size_t go = (base + (v ? gr : 0)) * 128 + c * 16;
            const char* src = mq ? (const char*)g_qlo : (const char*)g_qhi;
            cp16(sb + (mq ? SM_QLO : SM_QHI) + r * APB + c * 16, src + go, v);
        }
    }
    auto load_kv = [&](int i, int buf) {
        int k0 = i * 64;
        #pragma unroll
        for (int t = 0; t < 4; t++) {
            int chunk = tid + t * 256;          // 1024 chunks: k 512 | v 512
            int mat = chunk >> 9, rem = chunk & 511;
            int r = rem >> 3, c = rem & 7;
            int gr = k0 + r;
            bool v = gr < NTOK;
            size_t go = (base + (v ? gr : 0)) * 128 + c * 16;
            const char* src = mat ? (const char*)g_vh : (const char*)g_kh;
            cp16(sb + SM_ST0 + buf * STG_SZ + mat * (64 * APB) + r * APB + c * 16,
                 src + go, v);
        }
    };
    load_kv(0, 0);
    asm volatile("cp.async.commit_group;");
    load_kv(1, 1);
    asm volatile("cp.async.commit_group;");
    asm volatile("cp.async.wait_group 1;" ::: "memory");
    __syncthreads();

    float oacc[8][4] = {};
    float m_run[2] = {-1e30f, -1e30f};
    float l_run[2] = {0.f, 0.f};

    const int la_row = lane & 15, la_cs = (lane >> 4) * 16;
    const int m_ = lane >> 3, r_ = lane & 7;

    for (int i = 0; i < NKV; i++) {
        const uint32_t st = sb + SM_ST0 + (i & 1) * STG_SZ;
        const int k0 = i * 64;

        // ---- S = Qs K^T (Q pre-scaled; split: qh*k + ql*k) ----
        float sacc[8][4] = {};
        #pragma unroll
        for (int ks = 0; ks < 4; ks++) {
            uint32_t qh[4], ql[4];
            uint32_t qoff = (uint32_t)(wid * 16 + la_row) * APB + (uint32_t)(ks * 32 + la_cs);
            LDSM4(qh, sb + SM_QHI + qoff);
            LDSM4(ql, sb + SM_QLO + qoff);
            #pragma unroll
            for (int ntp = 0; ntp < 4; ntp++) {
                uint32_t kh[4];
                uint32_t koff = (uint32_t)(ntp * 16 + ((m_ >> 1) & 1) * 8 + r_) * APB
                              + (uint32_t)(ks * 32 + (m_ & 1) * 16);
                LDSM4(kh, st + OFF_K + koff);
                MMAFP(sacc[2 * ntp],     qh, kh[0], kh[1]);
                MMAFP(sacc[2 * ntp],     ql, kh[0], kh[1]);
                MMAFP(sacc[2 * ntp + 1], qh, kh[2], kh[3]);
                MMAFP(sacc[2 * ntp + 1], ql, kh[2], kh[3]);
            }
        }

        // ---- mask + online softmax ----
        float tm0 = -1e30f, tm1 = -1e30f;
        #pragma unroll
        for (int nt = 0; nt < 8; nt++) {
            int cbase = k0 + nt * 8 + (lane & 3) * 2;
            #pragma unroll
            for (int e = 0; e < 4; e++) {
                if (cbase + (e & 1) >= NTOK) sacc[nt][e] = -1e30f;
            }
            tm0 = fmaxf(tm0, fmaxf(sacc[nt][0], sacc[nt][1]));
            tm1 = fmaxf(tm1, fmaxf(sacc[nt][2], sacc[nt][3]));
        }
        tm0 = fmaxf(tm0, __shfl_xor_sync(0xffffffffu, tm0, 1));
        tm0 = fmaxf(tm0, __shfl_xor_sync(0xffffffffu, tm0, 2));
        tm1 = fmaxf(tm1, __shfl_xor_sync(0xffffffffu, tm1, 1));
        tm1 = fmaxf(tm1, __shfl_xor_sync(0xffffffffu, tm1, 2));
        float mn0 = fmaxf(m_run[0], tm0), mn1 = fmaxf(m_run[1], tm1);
        float al0 = __expf(m_run[0] - mn0), al1 = __expf(m_run[1] - mn1);
        m_run[0] = mn0; m_run[1] = mn1;

        float rs0 = 0.f, rs1 = 0.f;
        #pragma unroll
        for (int nt = 0; nt < 8; nt++) {
            sacc[nt][0] = __expf(sacc[nt][0] - mn0);
            sacc[nt][1] = __expf(sacc[nt][1] - mn0);
            sacc[nt][2] = __expf(sacc[nt][2] - mn1);
            sacc[nt][3] = __expf(sacc[nt][3] - mn1);
            rs0 += sacc[nt][0] + sacc[nt][1];
            rs1 += sacc[nt][2] + sacc[nt][3];
        }
        rs0 += __shfl_xor_sync(0xffffffffu, rs0, 1);
        rs0 += __shfl_xor_sync(0xffffffffu, rs0, 2);
        rs1 += __shfl_xor_sync(0xffffffffu, rs1, 1);
        rs1 += __shfl_xor_sync(0xffffffffu, rs1, 2);
        l_run[0] = l_run[0] * al0 + rs0;
        l_run[1] = l_run[1] * al1 + rs1;
        #pragma unroll
        for (int nt = 0; nt < 8; nt++) {
            oacc[nt][0] *= al0; oacc[nt][1] *= al0;
            oacc[nt][2] *= al1; oacc[nt][3] *= al1;
        }

        // ---- O += P V (split: ph*v + pl*v) ----
        #pragma unroll
        for (int kc = 0; kc < 4; kc++) {
            uint32_t ph[4], pl[4];
            split2h(sacc[2 * kc][0],     sacc[2 * kc][1],     ph[0], pl[0]);
            split2h(sacc[2 * kc][2],     sacc[2 * kc][3],     ph[1], pl[1]);
            split2h(sacc[2 * kc + 1][0], sacc[2 * kc + 1][1], ph[2], pl[2]);
            split2h(sacc[2 * kc + 1][2], sacc[2 * kc + 1][3], ph[3], pl[3]);
            #pragma unroll
            for (int ntp = 0; ntp < 4; ntp++) {
                uint32_t vh[4];
                uint32_t voff = (uint32_t)(kc * 16 + (m_ & 1) * 8 + r_) * APB
                              + (uint32_t)(ntp * 16 + ((m_ >> 1) & 1) * 8) * 2;
                LDSM4T(vh, st + OFF_V + voff);
                MMAFP(oacc[2 * ntp],     ph, vh[0], vh[1]);
                MMAFP(oacc[2 * ntp],     pl, vh[0], vh[1]);
                MMAFP(oacc[2 * ntp + 1], ph, vh[2], vh[3]);
                MMAFP(oacc[2 * ntp + 1], pl, vh[2], vh[3]);
            }
        }

        __syncthreads();
        if (i + 2 < NKV) {
            load_kv(i + 2, i & 1);
            asm volatile("cp.async.commit_group;");
        }
        if (i + 1 < NKV) {
            if (i + 2 < NKV) asm volatile("cp.async.wait_group 1;" ::: "memory");
            else             asm volatile("cp.async.wait_group 0;" ::: "memory");
            __syncthreads();
        }
    }

    // ---- epilogue -> ctx hi/lo fp16 ----
    float inv0 = 1.f / l_run[0], inv1 = 1.f / l_run[1];
    int rg0 = q0 + wid * 16 + (lane >> 2);
    int rg1 = rg0 + 8;
    int Cb = h * 64 + (lane & 3) * 2;
    #pragma unroll
    for (int nt = 0; nt < 8; nt++) {
        int C = Cb + nt * 8;
        if (rg0 < NTOK) {
            uint32_t hi, lo;
            split2h(oacc[nt][0] * inv0, oacc[nt][1] * inv0, hi, lo);
            size_t idx = (size_t)(b * NTOK + rg0) * DMODEL + C;
            *(uint32_t*)&g_chi[idx] = hi;
            *(uint32_t*)&g_clo[idx] = lo;
        }
        if (rg1 < NTOK) {
            uint32_t hi, lo;
            split2h(oacc[nt][2] * inv1, oacc[nt][3] * inv1, hi, lo);
            size_t idx = (size_t)(b * NTOK + rg1) * DMODEL + C;
            *(uint32_t*)&g_chi[idx] = hi;
            *(uint32_t*)&g_clo[idx] = lo;
        }
    }
}

// ---------------------------------------------------------------------------
extern "C" void kernel_launch(void* const* d_in, const int* in_sizes, int n_in,
                              void* d_out, int out_size)
{
    const float* hs   = (const float*)d_in[0];
    const float* sinp = (const float*)d_in[1];
    const float* cosp = (const float*)d_in[2];
    const float* Wq   = (const float*)d_in[3];
    const float* bq   = (const float*)d_in[4];
    const float* Wk   = (const float*)d_in[5];
    const float* bk   = (const float*)d_in[6];
    const float* Wv   = (const float*)d_in[7];
    const float* bv   = (const float*)d_in[8];
    const float* Wo   = (const float*)d_in[9];
    const float* bo   = (const float*)d_in[10];
    float* out = (float*)d_out;

    cudaFuncSetAttribute(wm_gemm_kernel,
                         cudaFuncAttributeMaxDynamicSharedMemorySize, GSM_BYTES);
    cudaFuncSetAttribute(attn_tc_kernel,
                         cudaFuncAttributeMaxDynamicSharedMemorySize, ATT_SMEM);

    split_x_kernel<<<(BNROWS * DMODEL) / 256, 256>>>(hs);
    split_w_kernel<<<(4 * DMODEL * DMODEL) / 256, 256>>>(Wq, Wk, Wv, Wo);
    biaspack_kernel<<<12, 256>>>(bq, bk, bv);

    wm_gemm_kernel<<<dim3(3 * DMODEL / 128, (BNROWS + 127) / 128), 256, GSM_BYTES>>>(
        bo, out, 1);

    prep_kernel<<<(3 * BATCH * NHEAD * NTOK * 32) / 256, 256>>>(sinp, cosp);

    attn_tc_kernel<<<dim3((NTOK + 127) / 128, NHEAD, BATCH), 256, ATT_SMEM>>>();

    wm_gemm_kernel<<<dim3(DMODEL / 128, (BNROWS + 127) / 128), 256, GSM_BYTES>>>(
        bo, out, 0);
}

// round 8
// speedup vs baseline: 4.2050x; 1.0022x over previous
#include <cuda_runtime.h>
#include <cuda_bf16.h>
#include <cuda_fp16.h>
#include <cstdint>

#define BATCH  16
#define NTOK   1029
#define NHEAD  16
#define HDIM   64
#define DMODEL 1024
#define PREFIX 5
#define BNROWS (BATCH * NTOK)   // 16464
#define BHN    (BATCH * NHEAD * NTOK)

// ---------------- scratch ----------------
__device__ float g_q[BHN * HDIM];
__device__ float g_k[BHN * HDIM];
__device__ float g_v[BHN * HDIM];

__device__ __half g_xhi[BNROWS * DMODEL];
__device__ __half g_xlo[BNROWS * DMODEL];
__device__ __half g_whi[3 * DMODEL * DMODEL];
__device__ __half g_wohi[DMODEL * DMODEL];
__device__ __half g_chi[BNROWS * DMODEL];
__device__ __half g_clo[BNROWS * DMODEL];
__device__ float g_bqkv[3 * DMODEL];

__device__ __half g_qhi[BHN * HDIM];
__device__ __half g_qlo[BHN * HDIM];
__device__ __half g_kh [BHN * HDIM];
__device__ __half g_vh [BHN * HDIM];

// ---------------- helpers ----------------
__device__ __forceinline__ uint32_t s2u(const void* p) {
    return (uint32_t)__cvta_generic_to_shared(p);
}
__device__ __forceinline__ void cp16(uint32_t d, const void* s, bool v) {
    asm volatile("cp.async.cg.shared.global [%0], [%1], 16, %2;"
                 :: "r"(d), "l"(s), "r"(v ? 16u : 0u));
}
#define LDSM4(r, addr) \
    asm volatile("ldmatrix.sync.aligned.m8n8.x4.shared.b16 {%0,%1,%2,%3}, [%4];" \
        : "=r"((r)[0]), "=r"((r)[1]), "=r"((r)[2]), "=r"((r)[3]) : "r"(addr))
#define LDSM4T(r, addr) \
    asm volatile("ldmatrix.sync.aligned.m8n8.x4.trans.shared.b16 {%0,%1,%2,%3}, [%4];" \
        : "=r"((r)[0]), "=r"((r)[1]), "=r"((r)[2]), "=r"((r)[3]) : "r"(addr))
#define MMAFP(c, a, b0, b1) \
    asm volatile("mma.sync.aligned.m16n8k16.row.col.f32.f16.f16.f32 " \
        "{%0,%1,%2,%3}, {%4,%5,%6,%7}, {%8,%9}, {%0,%1,%2,%3};" \
        : "+f"((c)[0]), "+f"((c)[1]), "+f"((c)[2]), "+f"((c)[3]) \
        : "r"((a)[0]), "r"((a)[1]), "r"((a)[2]), "r"((a)[3]), "r"(b0), "r"(b1))

__device__ __forceinline__ void split2h(float a, float b, uint32_t& hi, uint32_t& lo) {
    __half2 h = __floats2half2_rn(a, b);
    float ra = a - __low2float(h);
    float rb = b - __high2float(h);
    __half2 l = __floats2half2_rn(ra, rb);
    hi = *(uint32_t*)&h;
    lo = *(uint32_t*)&l;
}

// ---------------- conversion kernels ----------------
__global__ __launch_bounds__(256) void split_x_kernel(const float* __restrict__ in) {
    int i = blockIdx.x * 256 + threadIdx.x;
    float x = in[i];
    __half h = __float2half_rn(x);
    g_xhi[i] = h;
    g_xlo[i] = __float2half_rn(x - __half2float(h));
}
__global__ __launch_bounds__(256) void split_w_kernel(
    const float* __restrict__ Wq, const float* __restrict__ Wk,
    const float* __restrict__ Wv, const float* __restrict__ Wo) {
    int i = blockIdx.x * 256 + threadIdx.x;
    const int M1 = DMODEL * DMODEL;
    if (i < 3 * M1) {
        float x = (i < M1) ? Wq[i] : ((i < 2 * M1) ? Wk[i - M1] : Wv[i - 2 * M1]);
        g_whi[i] = __float2half_rn(x);
    } else {
        int j = i - 3 * M1;
        g_wohi[j] = __float2half_rn(Wo[j]);
    }
}
__global__ __launch_bounds__(256) void biaspack_kernel(
    const float* __restrict__ bq, const float* __restrict__ bk,
    const float* __restrict__ bv) {
    int i = blockIdx.x * 256 + threadIdx.x;
    if (i < 3 * DMODEL) {
        const float* s = (i < DMODEL) ? bq : ((i < 2 * DMODEL) ? bk : bv);
        g_bqkv[i] = s[i & (DMODEL - 1)];
    }
}

// ---------------- prep: RoPE + fp16 pack of q,k,v ----------------
__global__ __launch_bounds__(256) void prep_kernel(
    const float* __restrict__ sinp, const float* __restrict__ cosp)
{
    int idx = blockIdx.x * 256 + threadIdx.x;
    const int per = BATCH * NHEAD * NTOK * 32;
    int t = idx / per;
    int r = idx - t * per;
    int d = r & 31;
    int rowi = r >> 5;
    int n = rowi % NTOK;

    const float* src = (t == 0) ? g_q : ((t == 1) ? g_k : g_v);
    size_t base = (size_t)rowi * 64;
    float x1 = src[base + d], x2 = src[base + d + 32];
    float y1 = x1, y2 = x2;
    if (t < 2 && n >= PREFIX) {
        int pos = n - PREFIX;
        float c1 = cosp[pos * 64 + d],      s1 = sinp[pos * 64 + d];
        float c2 = cosp[pos * 64 + d + 32], s2 = sinp[pos * 64 + d + 32];
        y1 = x1 * c1 - x2 * s1;
        y2 = x2 * c2 + x1 * s2;
    }
    if (t == 0) {
        y1 *= 0.125f; y2 *= 0.125f;
        __half h1 = __float2half_rn(y1), h2 = __float2half_rn(y2);
        g_qhi[base + d]      = h1;
        g_qhi[base + d + 32] = h2;
        g_qlo[base + d]      = __float2half_rn(y1 - __half2float(h1));
        g_qlo[base + d + 32] = __float2half_rn(y2 - __half2float(h2));
    } else if (t == 1) {
        g_kh[base + d]      = __float2half_rn(y1);
        g_kh[base + d + 32] = __float2half_rn(y2);
    } else {
        g_vh[base + d]      = __float2half_rn(y1);
        g_vh[base + d + 32] = __float2half_rn(y2);
    }
}

// ---------------- warp-MMA fp16-split GEMM (hi-batch / lo-batch ILP) ----------------
#define BK 32
#define NKIT (DMODEL / BK)
#define SROWB 80
#define BUFB  (128 * SROWB)
#define STAGEB (3 * BUFB)
#define GSM_BYTES (3 * STAGEB)

__global__ __launch_bounds__(256) void wm_gemm_kernel(
    const float* __restrict__ bias_out, float* __restrict__ outp, int qkv_mode)
{
    extern __shared__ char sm[];
    const uint32_t sb = s2u(sm);
    const int tid = threadIdx.x;
    const int wid = tid >> 5, lane = tid & 31;
    const int warp_m = wid & 1, warp_n = wid >> 1;
    const int row0 = blockIdx.y * 128;
    const int col0 = blockIdx.x * 128;

    const __half* Ahi = qkv_mode ? g_xhi : g_chi;
    const __half* Alo = qkv_mode ? g_xlo : g_clo;
    const __half* Bh  = qkv_mode ? g_whi : g_wohi;

    float acc[4][4][4] = {};

    auto load_stage = [&](int kt, int buf) {
        const size_t kb = (size_t)kt * (BK * 2);
        const uint32_t s0 = sb + buf * STAGEB;
        #pragma unroll
        for (int t = 0; t < 6; t++) {
            int chunk = tid + t * 256;
            int mat = chunk >> 9, rem = chunk & 511;
            int r = rem >> 2, c = rem & 3;
            uint32_t so = (uint32_t)mat * BUFB + r * SROWB + c * 16;
            if (mat < 2) {
                int ga = row0 + r;
                bool av = ga < BNROWS;
                size_t go = (size_t)(av ? ga : 0) * (DMODEL * 2) + kb + c * 16;
                const char* src = mat ? (const char*)Alo : (const char*)Ahi;
                cp16(s0 + so, src + go, av);
            } else {
                size_t go = (size_t)(col0 + r) * (DMODEL * 2) + kb + c * 16;
                cp16(s0 + so, (const char*)Bh + go, true);
            }
        }
        asm volatile("cp.async.commit_group;");
    };

    load_stage(0, 0);
    load_stage(1, 1);

    const int a_row = warp_m * 64 + (lane & 15);
    const int a_colsel = (lane >> 4) << 3;
    const int b_row = warp_n * 32 + ((lane >> 4) & 1) * 8 + (lane & 7);
    const int b_colsel = ((lane >> 3) & 1) << 3;

    for (int kt = 0; kt < NKIT; kt++) {
        if (kt + 1 < NKIT) asm volatile("cp.async.wait_group 1;" ::: "memory");
        else               asm volatile("cp.async.wait_group 0;" ::: "memory");
        __syncthreads();
        if (kt + 2 < NKIT) load_stage(kt + 2, (kt + 2) % 3);

        const uint32_t s0 = sb + (kt % 3) * STAGEB;
        const uint32_t sA_hi = s0;
        const uint32_t sA_lo = s0 + BUFB;
        const uint32_t sB    = s0 + 2 * BUFB;

        #pragma unroll
        for (int kk = 0; kk < BK; kk += 16) {
            uint32_t ah[4][4], al[4][4], bh[2][4];
            #pragma unroll
            for (int mt = 0; mt < 4; mt++) {
                uint32_t off = (uint32_t)(a_row + mt * 16) * SROWB
                             + (uint32_t)(kk + a_colsel) * 2;
                LDSM4(ah[mt], sA_hi + off);
                LDSM4(al[mt], sA_lo + off);
            }
            #pragma unroll
            for (int p = 0; p < 2; p++) {
                uint32_t off = (uint32_t)(b_row + p * 16) * SROWB
                             + (uint32_t)(kk + b_colsel) * 2;
                LDSM4(bh[p], sB + off);
            }
            // hi batch: 16 independent MMAs
            #pragma unroll
            for (int mt = 0; mt < 4; mt++)
                #pragma unroll
                for (int nt = 0; nt < 4; nt++) {
                    int p = nt >> 1, q = (nt & 1) * 2;
                    MMAFP(acc[mt][nt], ah[mt], bh[p][q], bh[p][q + 1]);
                }
            // lo batch: 16 independent MMAs (RAW distance = 16)
            #pragma unroll
            for (int mt = 0; mt < 4; mt++)
                #pragma unroll
                for (int nt = 0; nt < 4; nt++) {
                    int p = nt >> 1, q = (nt & 1) * 2;
                    MMAFP(acc[mt][nt], al[mt], bh[p][q], bh[p][q + 1]);
                }
        }
    }

    const int crow = row0 + warp_m * 64 + (lane >> 2);
    const int ccol = col0 + warp_n * 32 + (lane & 3) * 2;
    #pragma unroll
    for (int mt = 0; mt < 4; mt++) {
        #pragma unroll
        for (int rr = 0; rr < 2; rr++) {
            int R = crow + mt * 16 + rr * 8;
            if (R >= BNROWS) continue;
            int b_ = R / NTOK, n = R - b_ * NTOK;
            #pragma unroll
            for (int nt = 0; nt < 4; nt++) {
                float v0 = acc[mt][nt][rr * 2 + 0];
                float v1 = acc[mt][nt][rr * 2 + 1];
                int C = ccol + nt * 8;
                if (qkv_mode) {
                    #pragma unroll
                    for (int e = 0; e < 2; e++) {
                        int Ce = C + e;
                        float val = (e ? v1 : v0) + g_bqkv[Ce];
                        int wsel = Ce >> 10, cl = Ce & 1023, h = cl >> 6, d = cl & 63;
                        float* dst = (wsel == 0) ? g_q : ((wsel == 1) ? g_k : g_v);
                        dst[(size_t)((b_ * NHEAD + h) * NTOK + n) * 64 + d] = val;
                    }
                } else {
                    outp[(size_t)R * DMODEL + C]     = v0 + bias_out[C];
                    outp[(size_t)R * DMODEL + C + 1] = v1 + bias_out[C + 1];
                }
            }
        }
    }
}

// ---------------- tensor-core flash attention (fp16 2-term, batched ILP) ----------------
#define APB 144
#define SM_QHI 0
#define SM_QLO (128 * APB)
#define SM_ST0 (2 * 128 * APB)
#define STG_SZ (2 * 64 * APB)
#define OFF_K 0
#define OFF_V (64 * APB)
#define ATT_SMEM (SM_ST0 + 2 * STG_SZ)
#define NKV 17

__global__ __launch_bounds__(256, 3) void attn_tc_kernel()
{
    extern __shared__ char sm[];
    const uint32_t sb = s2u(sm);
    const int tid = threadIdx.x;
    const int wid = tid >> 5, lane = tid & 31;
    const int b = blockIdx.z, h = blockIdx.y;
    const int q0 = blockIdx.x * 128;
    const size_t base = (size_t)(b * NHEAD + h) * NTOK;

    {
        #pragma unroll
        for (int t = 0; t < 8; t++) {
            int chunk = tid + t * 256;
            int mq = chunk >> 10, rem = chunk & 1023;
            int r = rem >> 3, c = rem & 7;
            int gr = q0 + r;
            bool v = gr < NTOK;
            size_t go = (base + (v ? gr : 0)) * 128 + c * 16;
            const char* src = mq ? (const char*)g_qlo : (const char*)g_qhi;
            cp16(sb + (mq ? SM_QLO : SM_QHI) + r * APB + c * 16, src + go, v);
        }
    }
    auto load_kv = [&](int i, int buf) {
        int k0 = i * 64;
        #pragma unroll
        for (int t = 0; t < 4; t++) {
            int chunk = tid + t * 256;
            int mat = chunk >> 9, rem = chunk & 511;
            int r = rem >> 3, c = rem & 7;
            int gr = k0 + r;
            bool v = gr < NTOK;
            size_t go = (base + (v ? gr : 0)) * 128 + c * 16;
            const char* src = mat ? (const char*)g_vh : (const char*)g_kh;
            cp16(sb + SM_ST0 + buf * STG_SZ + mat * (64 * APB) + r * APB + c * 16,
                 src + go, v);
        }
    };
    load_kv(0, 0);
    asm volatile("cp.async.commit_group;");
    load_kv(1, 1);
    asm volatile("cp.async.commit_group;");
    asm volatile("cp.async.wait_group 1;" ::: "memory");
    __syncthreads();

    float oacc[8][4] = {};
    float m_run[2] = {-1e30f, -1e30f};
    float l_run[2] = {0.f, 0.f};

    const int la_row = lane & 15, la_cs = (lane >> 4) * 16;
    const int m_ = lane >> 3, r_ = lane & 7;

    for (int i = 0; i < NKV; i++) {
        const uint32_t st = sb + SM_ST0 + (i & 1) * STG_SZ;
        const int k0 = i * 64;

        // ---- S = Qs K^T : per ks, load all K frags, hi batch (8 MMAs), lo batch (8) ----
        float sacc[8][4] = {};
        #pragma unroll
        for (int ks = 0; ks < 4; ks++) {
            uint32_t qh[4], ql[4];
            uint32_t qoff = (uint32_t)(wid * 16 + la_row) * APB + (uint32_t)(ks * 32 + la_cs);
            LDSM4(qh, sb + SM_QHI + qoff);
            LDSM4(ql, sb + SM_QLO + qoff);
            uint32_t kf[4][4];
            #pragma unroll
            for (int ntp = 0; ntp < 4; ntp++) {
                uint32_t koff = (uint32_t)(ntp * 16 + ((m_ >> 1) & 1) * 8 + r_) * APB
                              + (uint32_t)(ks * 32 + (m_ & 1) * 16);
                LDSM4(kf[ntp], st + OFF_K + koff);
            }
            #pragma unroll
            for (int ntp = 0; ntp < 4; ntp++) {
                MMAFP(sacc[2 * ntp],     qh, kf[ntp][0], kf[ntp][1]);
                MMAFP(sacc[2 * ntp + 1], qh, kf[ntp][2], kf[ntp][3]);
            }
            #pragma unroll
            for (int ntp = 0; ntp < 4; ntp++) {
                MMAFP(sacc[2 * ntp],     ql, kf[ntp][0], kf[ntp][1]);
                MMAFP(sacc[2 * ntp + 1], ql, kf[ntp][2], kf[ntp][3]);
            }
        }

        // ---- mask + online softmax ----
        float tm0 = -1e30f, tm1 = -1e30f;
        #pragma unroll
        for (int nt = 0; nt < 8; nt++) {
            int cbase = k0 + nt * 8 + (lane & 3) * 2;
            #pragma unroll
            for (int e = 0; e < 4; e++) {
                if (cbase + (e & 1) >= NTOK) sacc[nt][e] = -1e30f;
            }
            tm0 = fmaxf(tm0, fmaxf(sacc[nt][0], sacc[nt][1]));
            tm1 = fmaxf(tm1, fmaxf(sacc[nt][2], sacc[nt][3]));
        }
        tm0 = fmaxf(tm0, __shfl_xor_sync(0xffffffffu, tm0, 1));
        tm0 = fmaxf(tm0, __shfl_xor_sync(0xffffffffu, tm0, 2));
        tm1 = fmaxf(tm1, __shfl_xor_sync(0xffffffffu, tm1, 1));
        tm1 = fmaxf(tm1, __shfl_xor_sync(0xffffffffu, tm1, 2));
        float mn0 = fmaxf(m_run[0], tm0), mn1 = fmaxf(m_run[1], tm1);
        float al0 = __expf(m_run[0] - mn0), al1 = __expf(m_run[1] - mn1);
        m_run[0] = mn0; m_run[1] = mn1;

        float rs0 = 0.f, rs1 = 0.f;
        #pragma unroll
        for (int nt = 0; nt < 8; nt++) {
            sacc[nt][0] = __expf(sacc[nt][0] - mn0);
            sacc[nt][1] = __expf(sacc[nt][1] - mn0);
            sacc[nt][2] = __expf(sacc[nt][2] - mn1);
            sacc[nt][3] = __expf(sacc[nt][3] - mn1);
            rs0 += sacc[nt][0] + sacc[nt][1];
            rs1 += sacc[nt][2] + sacc[nt][3];
        }
        rs0 += __shfl_xor_sync(0xffffffffu, rs0, 1);
        rs0 += __shfl_xor_sync(0xffffffffu, rs0, 2);
        rs1 += __shfl_xor_sync(0xffffffffu, rs1, 1);
        rs1 += __shfl_xor_sync(0xffffffffu, rs1, 2);
        l_run[0] = l_run[0] * al0 + rs0;
        l_run[1] = l_run[1] * al1 + rs1;
        #pragma unroll
        for (int nt = 0; nt < 8; nt++) {
            oacc[nt][0] *= al0; oacc[nt][1] *= al0;
            oacc[nt][2] *= al1; oacc[nt][3] *= al1;
        }

        // ---- O += P V : per kc, load V frags, hi batch, lo batch ----
        #pragma unroll
        for (int kc = 0; kc < 4; kc++) {
            uint32_t ph[4], pl[4];
            split2h(sacc[2 * kc][0],     sacc[2 * kc][1],     ph[0], pl[0]);
            split2h(sacc[2 * kc][2],     sacc[2 * kc][3],     ph[1], pl[1]);
            split2h(sacc[2 * kc + 1][0], sacc[2 * kc + 1][1], ph[2], pl[2]);
            split2h(sacc[2 * kc + 1][2], sacc[2 * kc + 1][3], ph[3], pl[3]);
            uint32_t vf[4][4];
            #pragma unroll
            for (int ntp = 0; ntp < 4; ntp++) {
                uint32_t voff = (uint32_t)(kc * 16 + (m_ & 1) * 8 + r_) * APB
                              + (uint32_t)(ntp * 16 + ((m_ >> 1) & 1) * 8) * 2;
                LDSM4T(vf[ntp], st + OFF_V + voff);
            }
            #pragma unroll
            for (int ntp = 0; ntp < 4; ntp++) {
                MMAFP(oacc[2 * ntp],     ph, vf[ntp][0], vf[ntp][1]);
                MMAFP(oacc[2 * ntp + 1], ph, vf[ntp][2], vf[ntp][3]);
            }
            #pragma unroll
            for (int ntp = 0; ntp < 4; ntp++) {
                MMAFP(oacc[2 * ntp],     pl, vf[ntp][0], vf[ntp][1]);
                MMAFP(oacc[2 * ntp + 1], pl, vf[ntp][2], vf[ntp][3]);
            }
        }

        __syncthreads();
        if (i + 2 < NKV) {
            load_kv(i + 2, i & 1);
            asm volatile("cp.async.commit_group;");
        }
        if (i + 1 < NKV) {
            if (i + 2 < NKV) asm volatile("cp.async.wait_group 1;" ::: "memory");
            else             asm volatile("cp.async.wait_group 0;" ::: "memory");
            __syncthreads();
        }
    }

    float inv0 = 1.f / l_run[0], inv1 = 1.f / l_run[1];
    int rg0 = q0 + wid * 16 + (lane >> 2);
    int rg1 = rg0 + 8;
    int Cb = h * 64 + (lane & 3) * 2;
    #pragma unroll
    for (int nt = 0; nt < 8; nt++) {
        int C = Cb + nt * 8;
        if (rg0 < NTOK) {
            uint32_t hi, lo;
            split2h(oacc[nt][0] * inv0, oacc[nt][1] * inv0, hi, lo);
            size_t idx = (size_t)(b * NTOK + rg0) * DMODEL + C;
            *(uint32_t*)&g_chi[idx] = hi;
            *(uint32_t*)&g_clo[idx] = lo;
        }
        if (rg1 < NTOK) {
            uint32_t hi, lo;
            split2h(oacc[nt][2] * inv1, oacc[nt][3] * inv1, hi, lo);
            size_t idx = (size_t)(b * NTOK + rg1) * DMODEL + C;
            *(uint32_t*)&g_chi[idx] = hi;
            *(uint32_t*)&g_clo[idx] = lo;
        }
    }
}

// ---------------------------------------------------------------------------
extern "C" void kernel_launch(void* const* d_in, const int* in_sizes, int n_in,
                              void* d_out, int out_size)
{
    const float* hs   = (const float*)d_in[0];
    const float* sinp = (const float*)d_in[1];
    const float* cosp = (const float*)d_in[2];
    const float* Wq   = (const float*)d_in[3];
    const float* bq   = (const float*)d_in[4];
    const float* Wk   = (const float*)d_in[5];
    const float* bk   = (const float*)d_in[6];
    const float* Wv   = (const float*)d_in[7];
    const float* bv   = (const float*)d_in[8];
    const float* Wo   = (const float*)d_in[9];
    const float* bo   = (const float*)d_in[10];
    float* out = (float*)d_out;

    cudaFuncSetAttribute(wm_gemm_kernel,
                         cudaFuncAttributeMaxDynamicSharedMemorySize, GSM_BYTES);
    cudaFuncSetAttribute(attn_tc_kernel,
                         cudaFuncAttributeMaxDynamicSharedMemorySize, ATT_SMEM);

    split_x_kernel<<<(BNROWS * DMODEL) / 256, 256>>>(hs);
    split_w_kernel<<<(4 * DMODEL * DMODEL) / 256, 256>>>(Wq, Wk, Wv, Wo);
    biaspack_kernel<<<12, 256>>>(bq, bk, bv);

    wm_gemm_kernel<<<dim3(3 * DMODEL / 128, (BNROWS + 127) / 128), 256, GSM_BYTES>>>(
        bo, out, 1);

    prep_kernel<<<(3 * BATCH * NHEAD * NTOK * 32) / 256, 256>>>(sinp, cosp);

    attn_tc_kernel<<<dim3((NTOK + 127) / 128, NHEAD, BATCH), 256, ATT_SMEM>>>();

    wm_gemm_kernel<<<dim3(DMODEL / 128, (BNROWS + 127) / 128), 256, GSM_BYTES>>>(
        bo, out, 0);
}